// round 3
// baseline (speedup 1.0000x reference)
#include <cuda_runtime.h>
#include <cuda_fp16.h>
#include <math.h>
#include <stdint.h>

// Problem constants
#define BB 8
#define NN 1024
#define FF 128
#define GG 64
#define MM 4
#define EE 3
#define BE (BB*EE)        // 24
#define SLOTS (MM*GG)     // 256
#define ROWS (BB*NN)      // 8192
#define HC (MM*EE*GG)     // 768
#define L0C 256
#define L1C 256

// ---------------- scratch ----------------
__device__ float  d_Wt[EE*FF*SLOTS];
__device__ __half d_Wh[BE*NN*SLOTS];         // fp16 [be][n][m*64+g]
__device__ float  d_s1[BE*MM*NN];
__device__ float  d_s2[BE*MM*NN];
__device__ __half d_H [ROWS*HC];             // fp16 [b*N+n][m*192+e*64+g]
__device__ float  d_Hn[ROWS*FF];
__device__ float  d_bufA[ROWS*L0C];
__device__ float  d_bufB[ROWS*L0C];
__device__ float  d_stats[4*512];

// ---------------- mma/ldmatrix helpers ----------------
__device__ __forceinline__ uint32_t smem_u32(const void* p) {
    return (uint32_t)__cvta_generic_to_shared(p);
}
__device__ __forceinline__ void ldsm_x4(uint32_t* r, uint32_t addr) {
    asm volatile("ldmatrix.sync.aligned.m8n8.x4.shared.b16 {%0,%1,%2,%3}, [%4];"
        : "=r"(r[0]), "=r"(r[1]), "=r"(r[2]), "=r"(r[3]) : "r"(addr));
}
__device__ __forceinline__ void ldsm_x4t(uint32_t* r, uint32_t addr) {
    asm volatile("ldmatrix.sync.aligned.m8n8.x4.trans.shared.b16 {%0,%1,%2,%3}, [%4];"
        : "=r"(r[0]), "=r"(r[1]), "=r"(r[2]), "=r"(r[3]) : "r"(addr));
}
__device__ __forceinline__ void mma_f16(float* d, const uint32_t* a, uint32_t b0, uint32_t b1) {
    asm volatile(
        "mma.sync.aligned.m16n8k16.row.col.f32.f16.f16.f32 "
        "{%0,%1,%2,%3}, {%4,%5,%6,%7}, {%8,%9}, {%0,%1,%2,%3};"
        : "+f"(d[0]), "+f"(d[1]), "+f"(d[2]), "+f"(d[3])
        : "r"(a[0]), "r"(a[1]), "r"(a[2]), "r"(a[3]), "r"(b0), "r"(b1));
}
__device__ __forceinline__ void f8_to_h8(float4 a, float4 b, __half2* d) {
    d[0] = __floats2half2_rn(a.x, a.y);
    d[1] = __floats2half2_rn(a.z, a.w);
    d[2] = __floats2half2_rn(b.x, b.y);
    d[3] = __floats2half2_rn(b.z, b.w);
}

// ---------------- tiny utility kernels ----------------
__global__ void zero_kernel(float* p, int n) {
    int i = blockIdx.x*blockDim.x + threadIdx.x;
    if (i < n) p[i] = 0.f;
}

__global__ void wt_kernel(const float* __restrict__ Ws, float* __restrict__ Wt) {
    int idx = blockIdx.x*blockDim.x + threadIdx.x;
    if (idx >= EE*FF*SLOTS) return;
    int e = idx >> 15;
    int r = idx & 32767;
    int f = r >> 8;
    int c = r & 255;
    int m = c >> 6, g = c & 63;
    Wt[idx] = Ws[e*32768 + m*8192 + f*64 + g];
}

__global__ void edge_kernel(const int* __restrict__ A, float* __restrict__ out) {
    int idx = blockIdx.x*blockDim.x + threadIdx.x;
    if (idx >= BB*NN*(NN/16)) return;
    int j0 = (idx & 63) << 4;
    int bi = idx >> 6;
    int b = bi >> 10, i = bi & 1023;
    float v[48];
#pragma unroll
    for (int e = 0; e < 3; e++) {
        const int4* src = (const int4*)(A + (((long)(b*3+e)*NN + i) << 10) + j0);
#pragma unroll
        for (int k = 0; k < 4; k++) {
            int4 a = src[k];
            v[(k*4+0)*3+e] = (float)a.x;
            v[(k*4+1)*3+e] = (float)a.y;
            v[(k*4+2)*3+e] = (float)a.z;
            v[(k*4+3)*3+e] = (float)a.w;
        }
    }
    float4* o = (float4*)(out + (long)bi*3072 + (long)j0*3);
#pragma unroll
    for (int k = 0; k < 12; k++) o[k] = ((float4*)v)[k];
}

// s1[be][m][n] = sum_g Wh[be][n][m*64+g]*a1[e][m*64+g] (Wh fp16)
__global__ void s_kernel(const __half* __restrict__ Wh, const float* __restrict__ a1,
                         const float* __restrict__ a2,
                         float* __restrict__ s1, float* __restrict__ s2) {
    int gtid = blockIdx.x*blockDim.x + threadIdx.x;
    int wid = gtid >> 5;
    int lane = gtid & 31;
    if (wid >= BE*NN) return;
    int be = wid >> 10;
    int n  = wid & 1023;
    int e  = be % 3;
    const int4* w = (const int4*)(Wh + (long)wid*SLOTS);
    int4 raw = w[lane];                        // 8 halfs, g = lane*8..lane*8+7
    __half2 h[4];
    *(int4*)h = raw;
    const float4* A1 = (const float4*)(a1 + e*SLOTS + lane*8);
    const float4* A2 = (const float4*)(a2 + e*SLOTS + lane*8);
    float4 p1a = A1[0], p1b = A1[1];
    float4 p2a = A2[0], p2b = A2[1];
    float2 f0 = __half22float2(h[0]), f1 = __half22float2(h[1]);
    float2 f2 = __half22float2(h[2]), f3 = __half22float2(h[3]);
    float d1 = f0.x*p1a.x + f0.y*p1a.y + f1.x*p1a.z + f1.y*p1a.w
             + f2.x*p1b.x + f2.y*p1b.y + f3.x*p1b.z + f3.y*p1b.w;
    float d2 = f0.x*p2a.x + f0.y*p2a.y + f1.x*p2a.z + f1.y*p2a.w
             + f2.x*p2b.x + f2.y*p2b.y + f3.x*p2b.z + f3.y*p2b.w;
#pragma unroll
    for (int off = 4; off > 0; off >>= 1) {
        d1 += __shfl_down_sync(0xffffffffu, d1, off, 8);
        d2 += __shfl_down_sync(0xffffffffu, d2, off, 8);
    }
    if ((lane & 7) == 0) {
        int m = lane >> 3;
        s1[(be*4+m)*NN + n] = d1;
        s2[(be*4+m)*NN + n] = d2;
    }
}

// ---------------- attention v3: masked softmax + P@Wh via fp16 mma + ldmatrix ----------------
// grid (16, 24). 256 threads. smem (halfs): sWh[32][264] | sP[4][64][40] ; floats: sDen, sDen2
#define SWH_H 264
#define SP_H  40
#define SP_OFFH    (32*SWH_H)                       // 8448 halfs
#define SDEN_OFFH  (SP_OFFH + 4*64*SP_H)            // 18688 halfs
#define SDEN_OFFF  (SDEN_OFFH/2)                    // 9344 floats
#define SDEN2_OFFF (SDEN_OFFF + 1024)
#define ATT_SMEM_BYTES ((SDEN2_OFFF + 256)*4)       // 42496

__global__ void __launch_bounds__(256) att3_kernel(
        const int* __restrict__ A, const __half* __restrict__ Wh,
        const float* __restrict__ s1, const float* __restrict__ s2,
        __half* __restrict__ H) {
    extern __shared__ float smf[];
    __half* sWh  = (__half*)smf;
    __half* sP   = (__half*)smf + SP_OFFH;
    float* sDen  = smf + SDEN_OFFF;
    float* sDen2 = smf + SDEN2_OFFF;

    const int be = blockIdx.y;
    const int b  = be / 3, e = be % 3;
    const int i0 = blockIdx.x * 64;
    const int t  = threadIdx.x;
    const int lane = t & 31;
    const int w  = t >> 5;
    const int gid = lane >> 2, tig = lane & 3;

    const int ip = t >> 2;        // p-phase row 0..63
    const int jg = t & 3;         // p-phase j-chunk of 8
    const int am = w >> 1;        // head
    const int nh = (w & 1) * 32;  // n-half

    const int l16 = lane & 15, lhi = (lane >> 4) * 8;

    float s1v[4];
#pragma unroll
    for (int m = 0; m < 4; m++) s1v[m] = s1[(be*4+m)*NN + i0 + ip];

    float den[4] = {0.f,0.f,0.f,0.f};
    float acc[4][4][4];
#pragma unroll
    for (int mt = 0; mt < 4; mt++)
#pragma unroll
        for (int nt = 0; nt < 4; nt++)
#pragma unroll
            for (int q = 0; q < 4; q++) acc[mt][nt][q] = 0.f;

    const int*  Arow = A + ((long)be*NN + i0 + ip)*NN;
    const int4* WhB  = (const int4*)(Wh + (long)be*NN*SLOTS);   // 8 halfs per int4
    const float* s2b = s2 + be*4*NN;

    // precomputed ldmatrix smem addresses (byte)
    uint32_t aAbase = smem_u32(sP + (am*64 + l16)*SP_H + lhi);
    uint32_t aBbase = smem_u32(sWh + l16*SWH_H + am*64 + nh + lhi);

    for (int j0 = 0; j0 < NN; j0 += 32) {
        __syncthreads();
        // copy Wh tile [32 j][256 slots] fp16 (pure copy)
        {
            const int4* src = WhB + (long)j0*32;
#pragma unroll
            for (int k = 0; k < 4; k++) {
                int idx = t + k*256;
                int jj = idx >> 5, cq = idx & 31;
                *(int4*)(sWh + jj*SWH_H + cq*8) = src[jj*32 + cq];
            }
        }
        // p-phase: masked exp(lrelu(s1+s2)), 4 heads x 8 j per thread
        {
            int4 mk0 = *(const int4*)(Arow + j0 + jg*8);
            int4 mk1 = *(const int4*)(Arow + j0 + jg*8 + 4);
            int mv[8] = {mk0.x, mk0.y, mk0.z, mk0.w, mk1.x, mk1.y, mk1.z, mk1.w};
#pragma unroll
            for (int m = 0; m < 4; m++) {
                float4 sa = *(const float4*)(s2b + m*NN + j0 + jg*8);
                float4 sb = *(const float4*)(s2b + m*NN + j0 + jg*8 + 4);
                float sv[8] = {sa.x, sa.y, sa.z, sa.w, sb.x, sb.y, sb.z, sb.w};
                float pv[8];
#pragma unroll
                for (int q = 0; q < 8; q++) {
                    float x = s1v[m] + sv[q];
                    float l = (x >= 0.f) ? x : 0.01f*x;
                    float p = (mv[q] > 0) ? __expf(l) : 0.f;
                    den[m] += p;
                    pv[q] = p;
                }
                __half2 hp[4];
                hp[0] = __floats2half2_rn(pv[0], pv[1]);
                hp[1] = __floats2half2_rn(pv[2], pv[3]);
                hp[2] = __floats2half2_rn(pv[4], pv[5]);
                hp[3] = __floats2half2_rn(pv[6], pv[7]);
                *(int4*)(sP + (m*64 + ip)*SP_H + jg*8) = *(int4*)hp;
            }
        }
        __syncthreads();
        // mma phase: head am, n-half nh: P[64x32] @ Wh[32x32]
#pragma unroll
        for (int ks = 0; ks < 2; ks++) {
            uint32_t bfr[2][4];
#pragma unroll
            for (int ntp = 0; ntp < 2; ntp++)
                ldsm_x4t(bfr[ntp], aBbase + (ks*16*SWH_H + ntp*16)*2);
#pragma unroll
            for (int mt = 0; mt < 4; mt++) {
                uint32_t af[4];
                ldsm_x4(af, aAbase + (mt*16*SP_H + ks*16)*2);
#pragma unroll
                for (int nt = 0; nt < 4; nt++)
                    mma_f16(acc[mt][nt], af, bfr[nt>>1][(nt&1)*2], bfr[nt>>1][(nt&1)*2+1]);
            }
        }
    }
    // denominator reduce
    __syncthreads();
#pragma unroll
    for (int m = 0; m < 4; m++) sDen[(m*64 + ip)*4 + jg] = den[m];
    __syncthreads();
    {
        float s = sDen[t*4] + sDen[t*4+1] + sDen[t*4+2] + sDen[t*4+3];
        sDen2[t] = 1.f / fmaxf(s, 1e-30f);
    }
    __syncthreads();
    // epilogue: normalize, ELU, store fp16
#pragma unroll
    for (int mt = 0; mt < 4; mt++) {
        int r0 = mt*16 + gid;
        float inv0 = sDen2[am*64 + r0];
        float inv1 = sDen2[am*64 + r0 + 8];
        long row0 = (long)(b*NN) + i0 + r0;
        long row1 = row0 + 8;
#pragma unroll
        for (int nt = 0; nt < 4; nt++) {
            int col = am*192 + e*64 + nh + nt*8 + 2*tig;
            float v0 = acc[mt][nt][0]*inv0, v1 = acc[mt][nt][1]*inv0;
            float v2 = acc[mt][nt][2]*inv1, v3 = acc[mt][nt][3]*inv1;
            v0 = (v0 > 0.f) ? v0 : expm1f(v0);
            v1 = (v1 > 0.f) ? v1 : expm1f(v1);
            v2 = (v2 > 0.f) ? v2 : expm1f(v2);
            v3 = (v3 > 0.f) ? v3 : expm1f(v3);
            *(__half2*)(H + row0*HC + col) = __floats2half2_rn(v0, v1);
            *(__half2*)(H + row1*HC + col) = __floats2half2_rn(v2, v3);
        }
    }
}

// ---------------- fp16 mma GEMM: C = alpha*(A@B) + beta*R, optional bn-stats ----------------
// 64x64 tile, k-tile 32, 8 warps each 16m x 32n. ldmatrix fragments.
#define AS_H 40
#define BS_H 72
template <bool AH, bool CH>
__global__ void __launch_bounds__(256) gemm3_kernel(
        const void* __restrict__ Ain, const float* __restrict__ B, void* __restrict__ Cout,
        int M, int N, int K,
        long sA, long sB, long sC, int zDivA, int zModB,
        float alpha, const float* __restrict__ R, float beta,
        float* __restrict__ stats) {
    __shared__ __half As[64*AS_H];
    __shared__ __half Bs[32*BS_H];
    int z = blockIdx.z;
    const float*  Af = (const float*)Ain + (AH ? 0 : (long)(z / zDivA) * sA);
    const __half* Ah = (const __half*)Ain + (AH ? (long)(z / zDivA) * sA : 0);
    B += (long)(z % zModB) * sB;
    float*  Cf = (float*)Cout + (CH ? 0 : (long)z * sC);
    __half* Ch = (__half*)Cout + (CH ? (long)z * sC : 0);

    int n0 = blockIdx.x * 64, m0 = blockIdx.y * 64;
    int t = threadIdx.x, lane = t & 31, w = t >> 5;
    int gid = lane >> 2, tig = lane & 3;
    int mrow = (w & 3) * 16, ncol = (w >> 2) * 32;
    int l16 = lane & 15, lhi = (lane >> 4) * 8;

    uint32_t aA = smem_u32(As + (mrow + l16)*AS_H + lhi);
    uint32_t aB = smem_u32(Bs + l16*BS_H + ncol + lhi);

    float acc[4][4];
#pragma unroll
    for (int nt = 0; nt < 4; nt++)
#pragma unroll
        for (int q = 0; q < 4; q++) acc[nt][q] = 0.f;

    for (int k0 = 0; k0 < K; k0 += 32) {
        __syncthreads();
        // A tile 64x32 -> half
        {
            int m = t >> 2, kq = (t & 3) * 8;
            if (AH) {
                *(int4*)(As + m*AS_H + kq) = *(const int4*)(Ah + (long)(m0+m)*K + k0 + kq);
            } else {
                const float4* p = (const float4*)(Af + (long)(m0+m)*K + k0 + kq);
                f8_to_h8(p[0], p[1], (__half2*)(As + m*AS_H + kq));
            }
        }
        // B tile 32x64 -> half
        {
            int kk = t >> 3, nq = (t & 7) * 8;
            const float4* p = (const float4*)(B + (long)(k0+kk)*N + n0 + nq);
            f8_to_h8(p[0], p[1], (__half2*)(Bs + kk*BS_H + nq));
        }
        __syncthreads();
#pragma unroll
        for (int ks = 0; ks < 2; ks++) {
            uint32_t af[4];
            ldsm_x4(af, aA + ks*32);
            uint32_t bfr[2][4];
#pragma unroll
            for (int ntp = 0; ntp < 2; ntp++)
                ldsm_x4t(bfr[ntp], aB + (ks*16*BS_H + ntp*16)*2);
#pragma unroll
            for (int nt = 0; nt < 4; nt++)
                mma_f16(acc[nt], af, bfr[nt>>1][(nt&1)*2], bfr[nt>>1][(nt&1)*2+1]);
        }
    }
    // epilogue (fragment layout)
    float stS[4][2], stQ[4][2];
    long r0 = m0 + mrow + gid, r1 = r0 + 8;
#pragma unroll
    for (int nt = 0; nt < 4; nt++) {
        int c = n0 + ncol + nt*8 + 2*tig;
        float v0 = alpha*acc[nt][0], v1 = alpha*acc[nt][1];
        float v2 = alpha*acc[nt][2], v3 = alpha*acc[nt][3];
        if (R) {
            float2 ra = *(const float2*)(R + r0*N + c);
            float2 rb = *(const float2*)(R + r1*N + c);
            v0 += beta*ra.x; v1 += beta*ra.y; v2 += beta*rb.x; v3 += beta*rb.y;
        }
        if (CH) {
            *(__half2*)(Ch + r0*N + c) = __floats2half2_rn(v0, v1);
            *(__half2*)(Ch + r1*N + c) = __floats2half2_rn(v2, v3);
        } else {
            *(float2*)(Cf + r0*N + c) = make_float2(v0, v1);
            *(float2*)(Cf + r1*N + c) = make_float2(v2, v3);
        }
        stS[nt][0] = v0 + v2; stS[nt][1] = v1 + v3;
        stQ[nt][0] = v0*v0 + v2*v2; stQ[nt][1] = v1*v1 + v3*v3;
    }
    if (stats) {
#pragma unroll
        for (int nt = 0; nt < 4; nt++) {
#pragma unroll
            for (int cc = 0; cc < 2; cc++) {
                float s = stS[nt][cc], q = stQ[nt][cc];
#pragma unroll
                for (int off = 16; off >= 4; off >>= 1) {
                    s += __shfl_down_sync(0xffffffffu, s, off);
                    q += __shfl_down_sync(0xffffffffu, q, off);
                }
                if (lane < 4) {
                    int col = n0 + ncol + nt*8 + 2*lane + cc;
                    atomicAdd(&stats[col], s);
                    atomicAdd(&stats[N + col], q);
                }
            }
        }
    }
}

// ---------------- batchnorm normalize (+ optional ELU) ----------------
__global__ void norm_kernel(const float* __restrict__ Y, float* __restrict__ out,
                            const float* __restrict__ stats,
                            const float* __restrict__ g, const float* __restrict__ bb,
                            int N, int elu) {
    int idx = blockIdx.x*blockDim.x + threadIdx.x;
    if (idx >= ROWS*N) return;
    int col = idx & (N - 1);
    const float invM = 1.f / (float)ROWS;
    float mean = stats[col] * invM;
    float var  = stats[N + col] * invM - mean*mean;
    float ww = g[col] * rsqrtf(var + 1e-5f);
    float v = (Y[idx] - mean) * ww + bb[col];
    if (elu) v = (v > 0.f) ? v : expm1f(v);
    out[idx] = v;
}

// ---------------- launch ----------------
extern "C" void kernel_launch(void* const* d_in, const int* in_sizes, int n_in,
                              void* d_out, int out_size) {
    const int*   A      = (const int*)  d_in[0];
    const float* X      = (const float*)d_in[1];
    const float* Ws     = (const float*)d_in[3];
    const float* a1     = (const float*)d_in[4];
    const float* a2     = (const float*)d_in[5];
    const float* W1     = (const float*)d_in[6];
    const float* bn1_g  = (const float*)d_in[7];
    const float* bn1_b  = (const float*)d_in[8];
    const float* e_l0   = (const float*)d_in[9];
    const float* e_bn0g = (const float*)d_in[10];
    const float* e_bn0b = (const float*)d_in[11];
    const float* e_l1   = (const float*)d_in[12];
    const float* e_bn1g = (const float*)d_in[13];
    const float* e_bn1b = (const float*)d_in[14];
    const float* e_l2   = (const float*)d_in[15];
    const float* bn2_g  = (const float*)d_in[16];
    const float* bn2_b  = (const float*)d_in[17];
    float* out = (float*)d_out;

    float *pWt, *ps1, *ps2, *pHn, *pA, *pB, *pSt;
    __half *pWh, *pH;
    cudaGetSymbolAddress((void**)&pWt, d_Wt);
    cudaGetSymbolAddress((void**)&pWh, d_Wh);
    cudaGetSymbolAddress((void**)&ps1, d_s1);
    cudaGetSymbolAddress((void**)&ps2, d_s2);
    cudaGetSymbolAddress((void**)&pH,  d_H);
    cudaGetSymbolAddress((void**)&pHn, d_Hn);
    cudaGetSymbolAddress((void**)&pA,  d_bufA);
    cudaGetSymbolAddress((void**)&pB,  d_bufB);
    cudaGetSymbolAddress((void**)&pSt, d_stats);

    cudaFuncSetAttribute(att3_kernel, cudaFuncAttributeMaxDynamicSharedMemorySize, ATT_SMEM_BYTES);

    zero_kernel<<<8, 256>>>(pSt, 4*512);

    // edge_cat output (independent)
    edge_kernel<<<2048, 256>>>(A, out + ROWS*FF);

    // Ws relayout; Wh projection (fp32 in -> fp16 out); scores
    wt_kernel<<<384, 256>>>(Ws, pWt);
    gemm3_kernel<false, true><<<dim3(SLOTS/64, NN/64, BE), 256>>>(
        X, pWt, pWh, NN, SLOTS, FF,
        (long)NN*FF, (long)FF*SLOTS, (long)NN*SLOTS, EE, EE,
        1.f, nullptr, 0.f, nullptr);
    s_kernel<<<3072, 256>>>(pWh, a1, a2, ps1, ps2);

    // fused masked softmax + P@Wh + ELU -> H (fp16 mma)
    att3_kernel<<<dim3(NN/64, BE), 256, ATT_SMEM_BYTES>>>(A, pWh, ps1, ps2, pH);

    // H @ W1 * 0.5 + 0.5*X -> bufA, stats[0]; bn1 -> Hn
    gemm3_kernel<true, false><<<dim3(FF/64, ROWS/64, 1), 256>>>(
        pH, W1, pA, ROWS, FF, HC, 0,0,0, 1,1,
        0.5f, X, 0.5f, pSt + 0);
    norm_kernel<<<(ROWS*FF+255)/256, 256>>>(pA, pHn, pSt + 0, bn1_g, bn1_b, FF, 0);

    // Hn @ e_l0 -> bufA, stats[1]; elu(bn) -> bufB
    gemm3_kernel<false, false><<<dim3(L0C/64, ROWS/64, 1), 256>>>(
        pHn, e_l0, pA, ROWS, L0C, FF, 0,0,0, 1,1,
        1.f, nullptr, 0.f, pSt + 512);
    norm_kernel<<<(ROWS*L0C+255)/256, 256>>>(pA, pB, pSt + 512, e_bn0g, e_bn0b, L0C, 1);

    // Z0 @ e_l1 -> bufA, stats[2]; elu(bn) -> bufB
    gemm3_kernel<false, false><<<dim3(L1C/64, ROWS/64, 1), 256>>>(
        pB, e_l1, pA, ROWS, L1C, L0C, 0,0,0, 1,1,
        1.f, nullptr, 0.f, pSt + 1024);
    norm_kernel<<<(ROWS*L1C+255)/256, 256>>>(pA, pB, pSt + 1024, e_bn1g, e_bn1b, L1C, 1);

    // Z1 @ e_l2 + Hn -> bufA, stats[3]; bn2 -> out[0 : ROWS*FF]
    gemm3_kernel<false, false><<<dim3(FF/64, ROWS/64, 1), 256>>>(
        pB, e_l2, pA, ROWS, FF, L1C, 0,0,0, 1,1,
        1.f, pHn, 1.f, pSt + 1536);
    norm_kernel<<<(ROWS*FF+255)/256, 256>>>(pA, out, pSt + 1536, bn2_g, bn2_b, FF, 0);
}

// round 5
// speedup vs baseline: 1.4734x; 1.4734x over previous
#include <cuda_runtime.h>
#include <cuda_fp16.h>
#include <math.h>
#include <stdint.h>

// Problem constants
#define BB 8
#define NN 1024
#define FF 128
#define GG 64
#define MM 4
#define EE 3
#define BE (BB*EE)        // 24
#define SLOTS (MM*GG)     // 256
#define ROWS (BB*NN)      // 8192
#define HC (MM*EE*GG)     // 768
#define L0C 256
#define L1C 256

// ---------------- scratch ----------------
__device__ __half d_XH [ROWS*FF];
__device__ __half d_WtH[EE*FF*SLOTS];
__device__ __half d_W1H[HC*FF];
__device__ __half d_L0H[FF*L0C];
__device__ __half d_L1H[L0C*L1C];
__device__ __half d_L2H[L1C*FF];
__device__ __half d_Wh [BE*NN*SLOTS];        // [be][n][m*64+g]
__device__ __half d_H  [ROWS*HC];            // [b*N+n][m*192+e*64+g]
__device__ __half d_HnH[ROWS*FF];
__device__ float  d_HnF[ROWS*FF];
__device__ __half d_Z0h[ROWS*L0C];
__device__ __half d_Z1h[ROWS*L1C];
__device__ float  d_s1[BE*MM*NN];
__device__ float  d_s2[BE*MM*NN];
__device__ float  d_bufA[ROWS*L0C];
__device__ float  d_stats[4*512];

// ---------------- helpers ----------------
__device__ __forceinline__ uint32_t smem_u32(const void* p) {
    return (uint32_t)__cvta_generic_to_shared(p);
}
__device__ __forceinline__ void cp16(uint32_t dst, const void* src) {
    asm volatile("cp.async.cg.shared.global [%0], [%1], 16;" :: "r"(dst), "l"(src) : "memory");
}
#define CP_COMMIT asm volatile("cp.async.commit_group;" ::: "memory")
#define CP_WAIT1  asm volatile("cp.async.wait_group 1;" ::: "memory")
#define CP_WAIT0  asm volatile("cp.async.wait_group 0;" ::: "memory")

__device__ __forceinline__ void ldsm_x4(uint32_t* r, uint32_t addr) {
    asm volatile("ldmatrix.sync.aligned.m8n8.x4.shared.b16 {%0,%1,%2,%3}, [%4];"
        : "=r"(r[0]), "=r"(r[1]), "=r"(r[2]), "=r"(r[3]) : "r"(addr));
}
__device__ __forceinline__ void ldsm_x4t(uint32_t* r, uint32_t addr) {
    asm volatile("ldmatrix.sync.aligned.m8n8.x4.trans.shared.b16 {%0,%1,%2,%3}, [%4];"
        : "=r"(r[0]), "=r"(r[1]), "=r"(r[2]), "=r"(r[3]) : "r"(addr));
}
__device__ __forceinline__ void mma_f16(float* d, const uint32_t* a, uint32_t b0, uint32_t b1) {
    asm volatile(
        "mma.sync.aligned.m16n8k16.row.col.f32.f16.f16.f32 "
        "{%0,%1,%2,%3}, {%4,%5,%6,%7}, {%8,%9}, {%0,%1,%2,%3};"
        : "+f"(d[0]), "+f"(d[1]), "+f"(d[2]), "+f"(d[3])
        : "r"(a[0]), "r"(a[1]), "r"(a[2]), "r"(a[3]), "r"(b0), "r"(b1));
}

// ---------------- tiny utility kernels ----------------
__global__ void zero3_kernel(float4* a, int na, float4* b, int nb, float4* c, int nc) {
    int i = blockIdx.x*blockDim.x + threadIdx.x;
    float4 z = make_float4(0.f,0.f,0.f,0.f);
    if (i < na) a[i] = z;
    else if ((i -= na) < nb) b[i] = z;
    else if ((i -= nb) < nc) c[i] = z;
}

// convert X, W1, e_l0, e_l1, e_l2 to fp16 (vectorized x4)
#define CVT_NX (ROWS*FF)
#define CVT_NW1 (HC*FF)
#define CVT_NL0 (FF*L0C)
#define CVT_NL1 (L0C*L1C)
#define CVT_NL2 (L1C*FF)
#define CVT_TOT4 ((CVT_NX+CVT_NW1+CVT_NL0+CVT_NL1+CVT_NL2)/4)
__global__ void cvt_kernel(const float* __restrict__ X, const float* __restrict__ W1,
                           const float* __restrict__ L0, const float* __restrict__ L1,
                           const float* __restrict__ L2) {
    int i4 = blockIdx.x*blockDim.x + threadIdx.x;
    if (i4 >= CVT_TOT4) return;
    int i = i4*4;
    const float* src; __half* dst;
    if (i < CVT_NX) { src = X; dst = d_XH; }
    else if ((i -= CVT_NX) < CVT_NW1) { src = W1; dst = d_W1H; }
    else if ((i -= CVT_NW1) < CVT_NL0) { src = L0; dst = d_L0H; }
    else if ((i -= CVT_NL0) < CVT_NL1) { src = L1; dst = d_L1H; }
    else { i -= CVT_NL1; src = L2; dst = d_L2H; }
    float4 v = *(const float4*)(src + i);
    __half2 h0 = __floats2half2_rn(v.x, v.y);
    __half2 h1 = __floats2half2_rn(v.z, v.w);
    *(__half2*)(dst + i) = h0;
    *(__half2*)(dst + i + 2) = h1;
}

// WtH[e][f][m*64+g] = (half)Ws[e][(m*128+f)*64+g]
__global__ void wt_kernel(const float* __restrict__ Ws) {
    int idx = blockIdx.x*blockDim.x + threadIdx.x;
    if (idx >= EE*FF*SLOTS) return;
    int e = idx >> 15;
    int r = idx & 32767;
    int f = r >> 8;
    int c = r & 255;
    int m = c >> 6, g = c & 63;
    d_WtH[idx] = __float2half(Ws[e*32768 + m*8192 + f*64 + g]);
}

__global__ void edge_kernel(const int* __restrict__ A, float* __restrict__ out) {
    int idx = blockIdx.x*blockDim.x + threadIdx.x;
    if (idx >= BB*NN*(NN/16)) return;
    int j0 = (idx & 63) << 4;
    int bi = idx >> 6;
    int b = bi >> 10, i = bi & 1023;
    float v[48];
#pragma unroll
    for (int e = 0; e < 3; e++) {
        const int4* src = (const int4*)(A + (((long)(b*3+e)*NN + i) << 10) + j0);
#pragma unroll
        for (int k = 0; k < 4; k++) {
            int4 a = src[k];
            v[(k*4+0)*3+e] = (float)a.x;
            v[(k*4+1)*3+e] = (float)a.y;
            v[(k*4+2)*3+e] = (float)a.z;
            v[(k*4+3)*3+e] = (float)a.w;
        }
    }
    float4* o = (float4*)(out + (long)bi*3072 + (long)j0*3);
#pragma unroll
    for (int k = 0; k < 12; k++) o[k] = ((float4*)v)[k];
}

// ---------------- gemm4: fp16 x fp16 -> fp32, cp.async 2-stage pipeline ----------------
// 64x64 tile, k-tile 32, 8 warps each 16m x 32n. Optional residual/stats/s1s2-dot fusion.
#define AS_H 40
#define BS_H 72
template <int CH>
__global__ void __launch_bounds__(256) gemm4_kernel(
        const __half* __restrict__ Ah, const __half* __restrict__ Bh, void* __restrict__ Cout,
        int M, int N, int K,
        long sA, long sB, long sC, int zDivA, int zModB,
        float alpha, const float* __restrict__ R, float beta,
        float* __restrict__ stats,
        const float* __restrict__ a1, const float* __restrict__ a2,
        float* __restrict__ s1o, float* __restrict__ s2o) {
    __shared__ __half As[2][64*AS_H];
    __shared__ __half Bs[2][32*BS_H];
    int z = blockIdx.z;
    Ah += (long)(z / zDivA) * sA;
    Bh += (long)(z % zModB) * sB;
    float*  Cf = (float*)Cout + (CH ? 0 : (long)z * sC);
    __half* Ch = (__half*)Cout + (CH ? (long)z * sC : 0);

    int n0 = blockIdx.x * 64, m0 = blockIdx.y * 64;
    int t = threadIdx.x, lane = t & 31, w = t >> 5;
    int gid = lane >> 2, tig = lane & 3;
    int mrow = (w & 3) * 16, ncol = (w >> 2) * 32;
    int l16 = lane & 15, lhi = (lane >> 4) * 8;

    // cp.async chunk positions
    int am_ = t >> 2, akq = (t & 3) * 8;           // A: 1 chunk/thread
    int bkk = t >> 3, bnq = (t & 7) * 8;           // B: 1 chunk/thread
    long aoff = (long)(m0 + am_)*K + akq;
    long boff = (long)bkk*N + n0 + bnq;
    uint32_t adst[2] = { smem_u32(&As[0][am_*AS_H + akq]), smem_u32(&As[1][am_*AS_H + akq]) };
    uint32_t bdst[2] = { smem_u32(&Bs[0][bkk*BS_H + bnq]), smem_u32(&Bs[1][bkk*BS_H + bnq]) };
    uint32_t aA[2] = { smem_u32(&As[0][(mrow+l16)*AS_H + lhi]), smem_u32(&As[1][(mrow+l16)*AS_H + lhi]) };
    uint32_t aB[2] = { smem_u32(&Bs[0][l16*BS_H + ncol + lhi]), smem_u32(&Bs[1][l16*BS_H + ncol + lhi]) };

    float acc[4][4];
#pragma unroll
    for (int nt = 0; nt < 4; nt++)
#pragma unroll
        for (int q = 0; q < 4; q++) acc[nt][q] = 0.f;

    int T = K >> 5;
    // prologue: tile 0 -> stage 0
    cp16(adst[0], Ah + aoff);
    cp16(bdst[0], Bh + boff);
    CP_COMMIT;

    for (int tk = 0; tk < T; tk++) {
        int st = tk & 1;
        __syncthreads();
        if (tk+1 < T) {
            int k0 = (tk+1) << 5;
            cp16(adst[st^1], Ah + aoff + k0);
            cp16(bdst[st^1], Bh + boff + (long)k0*N);
            CP_COMMIT;
            CP_WAIT1;
        } else {
            CP_WAIT0;
        }
        __syncthreads();
#pragma unroll
        for (int ks = 0; ks < 2; ks++) {
            uint32_t af[4];
            ldsm_x4(af, aA[st] + ks*32);
            uint32_t bfr[2][4];
#pragma unroll
            for (int ntp = 0; ntp < 2; ntp++)
                ldsm_x4t(bfr[ntp], aB[st] + (ks*16*BS_H + ntp*16)*2);
#pragma unroll
            for (int nt = 0; nt < 4; nt++)
                mma_f16(acc[nt], af, bfr[nt>>1][(nt&1)*2], bfr[nt>>1][(nt&1)*2+1]);
        }
    }
    // epilogue (fragment layout)
    float stS[4][2], stQ[4][2];
    float d1a = 0.f, d1b = 0.f, d2a = 0.f, d2b = 0.f;
    const float* a1e = a1 ? a1 + (z % 3)*SLOTS : nullptr;
    const float* a2e = a2 ? a2 + (z % 3)*SLOTS : nullptr;
    long r0 = m0 + mrow + gid, r1 = r0 + 8;
#pragma unroll
    for (int nt = 0; nt < 4; nt++) {
        int c = n0 + ncol + nt*8 + 2*tig;
        float v0 = alpha*acc[nt][0], v1 = alpha*acc[nt][1];
        float v2 = alpha*acc[nt][2], v3 = alpha*acc[nt][3];
        if (R) {
            float2 ra = *(const float2*)(R + r0*N + c);
            float2 rb = *(const float2*)(R + r1*N + c);
            v0 += beta*ra.x; v1 += beta*ra.y; v2 += beta*rb.x; v3 += beta*rb.y;
        }
        if (CH) {
            *(__half2*)(Ch + r0*N + c) = __floats2half2_rn(v0, v1);
            *(__half2*)(Ch + r1*N + c) = __floats2half2_rn(v2, v3);
        } else {
            *(float2*)(Cf + r0*N + c) = make_float2(v0, v1);
            *(float2*)(Cf + r1*N + c) = make_float2(v2, v3);
        }
        if (a1e) {
            float w10 = a1e[c], w11 = a1e[c+1];
            float w20 = a2e[c], w21 = a2e[c+1];
            d1a += v0*w10 + v1*w11; d1b += v2*w10 + v3*w11;
            d2a += v0*w20 + v1*w21; d2b += v2*w20 + v3*w21;
        }
        stS[nt][0] = v0 + v2; stS[nt][1] = v1 + v3;
        stQ[nt][0] = v0*v0 + v2*v2; stQ[nt][1] = v1*v1 + v3*v3;
    }
    if (a1e) {
        d1a += __shfl_down_sync(0xffffffffu, d1a, 1); d1a += __shfl_down_sync(0xffffffffu, d1a, 2);
        d1b += __shfl_down_sync(0xffffffffu, d1b, 1); d1b += __shfl_down_sync(0xffffffffu, d1b, 2);
        d2a += __shfl_down_sync(0xffffffffu, d2a, 1); d2a += __shfl_down_sync(0xffffffffu, d2a, 2);
        d2b += __shfl_down_sync(0xffffffffu, d2b, 1); d2b += __shfl_down_sync(0xffffffffu, d2b, 2);
        if (tig == 0) {
            int mhead = n0 >> 6;
            int base = (z*4 + mhead)*NN;
            atomicAdd(&s1o[base + r0], d1a);
            atomicAdd(&s1o[base + r1], d1b);
            atomicAdd(&s2o[base + r0], d2a);
            atomicAdd(&s2o[base + r1], d2b);
        }
    }
    if (stats) {
#pragma unroll
        for (int nt = 0; nt < 4; nt++) {
#pragma unroll
            for (int cc = 0; cc < 2; cc++) {
                float s = stS[nt][cc], q = stQ[nt][cc];
#pragma unroll
                for (int off = 16; off >= 4; off >>= 1) {
                    s += __shfl_down_sync(0xffffffffu, s, off);
                    q += __shfl_down_sync(0xffffffffu, q, off);
                }
                if (lane < 4) {
                    int col = n0 + ncol + nt*8 + 2*lane + cc;
                    atomicAdd(&stats[col], s);
                    atomicAdd(&stats[N + col], q);
                }
            }
        }
    }
}

// ---------------- attention v4: i-tile 32, cp.async 2-stage Wh pipeline ----------------
#define SWH_H 264
#define SP_H  40
__global__ void __launch_bounds__(256, 3) att4_kernel(
        const int* __restrict__ A, const __half* __restrict__ Wh,
        const float* __restrict__ s1, const float* __restrict__ s2,
        __half* __restrict__ H) {
    __shared__ __half sWh[2][32*SWH_H];
    __shared__ __half sP[4*32*SP_H];
    __shared__ float sDen[1024];
    __shared__ float sDen2[128];

    const int be = blockIdx.y;
    const int b  = be / 3, e = be % 3;
    const int i0 = blockIdx.x * 32;
    const int t  = threadIdx.x;
    const int lane = t & 31;
    const int w  = t >> 5;
    const int gid = lane >> 2, tig = lane & 3;
    const int l16 = lane & 15, lhi = (lane >> 4) * 8;

    const int ip = t >> 3;        // p-phase row 0..31
    const int jg = t & 7;         // p-phase j-chunk of 4
    const int am = w >> 1;        // head
    const int nh = (w & 1) * 32;  // n-half

    float s1v[4];
#pragma unroll
    for (int m = 0; m < 4; m++) s1v[m] = s1[(be*4+m)*NN + i0 + ip];

    float den[4] = {0.f,0.f,0.f,0.f};
    float acc[2][4][4];
#pragma unroll
    for (int mt = 0; mt < 2; mt++)
#pragma unroll
        for (int nt = 0; nt < 4; nt++)
#pragma unroll
            for (int q = 0; q < 4; q++) acc[mt][nt][q] = 0.f;

    const int*   Arow = A + ((long)be*NN + i0 + ip)*NN;
    const __half* WhB = Wh + (long)be*NN*SLOTS;
    const float* s2b  = s2 + be*4*NN;

    // cp.async chunk positions: 4 chunks per thread (tile = 1024 x 16B)
    int off[4];
    uint32_t wdst[2][4];
#pragma unroll
    for (int k = 0; k < 4; k++) {
        int idx = t + k*256;
        int jj = idx >> 5, cq = idx & 31;
        off[k] = jj*256 + cq*8;
        wdst[0][k] = smem_u32(&sWh[0][jj*SWH_H + cq*8]);
        wdst[1][k] = smem_u32(&sWh[1][jj*SWH_H + cq*8]);
    }
    uint32_t aP = smem_u32(&sP[(am*32 + l16)*SP_H + lhi]);
    uint32_t aW[2] = { smem_u32(&sWh[0][l16*SWH_H + am*64 + nh + lhi]),
                       smem_u32(&sWh[1][l16*SWH_H + am*64 + nh + lhi]) };

    // prologue: tile 0 -> stage 0
#pragma unroll
    for (int k = 0; k < 4; k++) cp16(wdst[0][k], WhB + off[k]);
    CP_COMMIT;

    for (int jt = 0; jt < 32; jt++) {
        const int j0 = jt << 5;
        const int st = jt & 1;
        __syncthreads();                 // mma(jt-1) complete everywhere
        if (jt+1 < 32) {
            const __half* src = WhB + (long)(j0+32)*SLOTS;
#pragma unroll
            for (int k = 0; k < 4; k++) cp16(wdst[st^1][k], src + off[k]);
            CP_COMMIT;
        }
        // p-phase: masked exp(lrelu(s1+s2)), 4 heads x 4 j per thread
        {
            int4 mk = *(const int4*)(Arow + j0 + jg*4);
#pragma unroll
            for (int m = 0; m < 4; m++) {
                float4 s4 = *(const float4*)(s2b + m*NN + j0 + jg*4);
                float x0 = s1v[m]+s4.x, x1 = s1v[m]+s4.y, x2 = s1v[m]+s4.z, x3 = s1v[m]+s4.w;
                x0 = (x0 >= 0.f) ? x0 : 0.01f*x0;
                x1 = (x1 >= 0.f) ? x1 : 0.01f*x1;
                x2 = (x2 >= 0.f) ? x2 : 0.01f*x2;
                x3 = (x3 >= 0.f) ? x3 : 0.01f*x3;
                float p0 = (mk.x > 0) ? __expf(x0) : 0.f;
                float p1 = (mk.y > 0) ? __expf(x1) : 0.f;
                float p2 = (mk.z > 0) ? __expf(x2) : 0.f;
                float p3 = (mk.w > 0) ? __expf(x3) : 0.f;
                den[m] += (p0+p1) + (p2+p3);
                __half2 h0 = __floats2half2_rn(p0, p1);
                __half2 h1 = __floats2half2_rn(p2, p3);
                __half2 hp[2] = {h0, h1};
                *(uint2*)&sP[(m*32 + ip)*SP_H + jg*4] = *(uint2*)hp;
            }
        }
        if (jt+1 < 32) { CP_WAIT1; } else { CP_WAIT0; }
        __syncthreads();                 // sWh[st] + sP visible
        // mma: head am, n-half nh: P[32x32] @ Wh[32x32]
#pragma unroll
        for (int ks = 0; ks < 2; ks++) {
            uint32_t bfr[2][4];
#pragma unroll
            for (int ntp = 0; ntp < 2; ntp++)
                ldsm_x4t(bfr[ntp], aW[st] + (ks*16*SWH_H + ntp*16)*2);
#pragma unroll
            for (int mt = 0; mt < 2; mt++) {
                uint32_t af[4];
                ldsm_x4(af, aP + (mt*16*SP_H + ks*16)*2);
#pragma unroll
                for (int nt = 0; nt < 4; nt++)
                    mma_f16(acc[mt][nt], af, bfr[nt>>1][(nt&1)*2], bfr[nt>>1][(nt&1)*2+1]);
            }
        }
    }
    // denominator reduce
    __syncthreads();
#pragma unroll
    for (int m = 0; m < 4; m++) sDen[(m*32 + ip)*8 + jg] = den[m];
    __syncthreads();
    if (t < 128) {
        float s = 0.f;
#pragma unroll
        for (int r = 0; r < 8; r++) s += sDen[t*8 + r];
        sDen2[t] = 1.f / fmaxf(s, 1e-30f);
    }
    __syncthreads();
    // epilogue: normalize, ELU, store fp16
#pragma unroll
    for (int mt = 0; mt < 2; mt++) {
        int r0 = mt*16 + gid;
        float inv0 = sDen2[am*32 + r0];
        float inv1 = sDen2[am*32 + r0 + 8];
        long row0 = (long)(b*NN) + i0 + r0;
        long row1 = row0 + 8;
#pragma unroll
        for (int nt = 0; nt < 4; nt++) {
            int col = am*192 + e*64 + nh + nt*8 + 2*tig;
            float v0 = acc[mt][nt][0]*inv0, v1 = acc[mt][nt][1]*inv0;
            float v2 = acc[mt][nt][2]*inv1, v3 = acc[mt][nt][3]*inv1;
            v0 = (v0 > 0.f) ? v0 : expm1f(v0);
            v1 = (v1 > 0.f) ? v1 : expm1f(v1);
            v2 = (v2 > 0.f) ? v2 : expm1f(v2);
            v3 = (v3 > 0.f) ? v3 : expm1f(v3);
            *(__half2*)(H + row0*HC + col) = __floats2half2_rn(v0, v1);
            *(__half2*)(H + row1*HC + col) = __floats2half2_rn(v2, v3);
        }
    }
}

// ---------------- batchnorm normalize: fp32 in -> fp16 (+opt fp32) out ----------------
__global__ void norm2_kernel(const float* __restrict__ Y, __half* __restrict__ oh,
                             float* __restrict__ of,
                             const float* __restrict__ stats,
                             const float* __restrict__ g, const float* __restrict__ bb,
                             int N, int elu) {
    int i4 = blockIdx.x*blockDim.x + threadIdx.x;
    if (i4 >= ROWS*N/4) return;
    int i = i4*4;
    int col = i & (N - 1);
    const float invM = 1.f / (float)ROWS;
    float4 y = *(const float4*)(Y + i);
    float4 sm = *(const float4*)(stats + col);
    float4 sq = *(const float4*)(stats + N + col);
    float4 gg = *(const float4*)(g + col);
    float4 bv = *(const float4*)(bb + col);
    float m0 = sm.x*invM, m1 = sm.y*invM, m2 = sm.z*invM, m3 = sm.w*invM;
    float w0 = gg.x * rsqrtf(sq.x*invM - m0*m0 + 1e-5f);
    float w1 = gg.y * rsqrtf(sq.y*invM - m1*m1 + 1e-5f);
    float w2 = gg.z * rsqrtf(sq.z*invM - m2*m2 + 1e-5f);
    float w3 = gg.w * rsqrtf(sq.w*invM - m3*m3 + 1e-5f);
    float v0 = (y.x - m0)*w0 + bv.x;
    float v1 = (y.y - m1)*w1 + bv.y;
    float v2 = (y.z - m2)*w2 + bv.z;
    float v3 = (y.w - m3)*w3 + bv.w;
    if (elu) {
        v0 = (v0 > 0.f) ? v0 : expm1f(v0);
        v1 = (v1 > 0.f) ? v1 : expm1f(v1);
        v2 = (v2 > 0.f) ? v2 : expm1f(v2);
        v3 = (v3 > 0.f) ? v3 : expm1f(v3);
    }
    if (oh) {
        *(__half2*)(oh + i)     = __floats2half2_rn(v0, v1);
        *(__half2*)(oh + i + 2) = __floats2half2_rn(v2, v3);
    }
    if (of) *(float4*)(of + i) = make_float4(v0, v1, v2, v3);
}

// ---------------- launch ----------------
extern "C" void kernel_launch(void* const* d_in, const int* in_sizes, int n_in,
                              void* d_out, int out_size) {
    const int*   A      = (const int*)  d_in[0];
    const float* X      = (const float*)d_in[1];
    const float* Ws     = (const float*)d_in[3];
    const float* a1     = (const float*)d_in[4];
    const float* a2     = (const float*)d_in[5];
    const float* W1     = (const float*)d_in[6];
    const float* bn1_g  = (const float*)d_in[7];
    const float* bn1_b  = (const float*)d_in[8];
    const float* e_l0   = (const float*)d_in[9];
    const float* e_bn0g = (const float*)d_in[10];
    const float* e_bn0b = (const float*)d_in[11];
    const float* e_l1   = (const float*)d_in[12];
    const float* e_bn1g = (const float*)d_in[13];
    const float* e_bn1b = (const float*)d_in[14];
    const float* e_l2   = (const float*)d_in[15];
    const float* bn2_g  = (const float*)d_in[16];
    const float* bn2_b  = (const float*)d_in[17];
    float* out = (float*)d_out;

    float *ps1, *ps2, *pHnF, *pA, *pSt;
    __half *pXH, *pWtH, *pW1H, *pL0H, *pL1H, *pL2H, *pWh, *pH, *pHnH, *pZ0, *pZ1;
    cudaGetSymbolAddress((void**)&pXH,  d_XH);
    cudaGetSymbolAddress((void**)&pWtH, d_WtH);
    cudaGetSymbolAddress((void**)&pW1H, d_W1H);
    cudaGetSymbolAddress((void**)&pL0H, d_L0H);
    cudaGetSymbolAddress((void**)&pL1H, d_L1H);
    cudaGetSymbolAddress((void**)&pL2H, d_L2H);
    cudaGetSymbolAddress((void**)&pWh,  d_Wh);
    cudaGetSymbolAddress((void**)&pH,   d_H);
    cudaGetSymbolAddress((void**)&pHnH, d_HnH);
    cudaGetSymbolAddress((void**)&pHnF, d_HnF);
    cudaGetSymbolAddress((void**)&pZ0,  d_Z0h);
    cudaGetSymbolAddress((void**)&pZ1,  d_Z1h);
    cudaGetSymbolAddress((void**)&ps1,  d_s1);
    cudaGetSymbolAddress((void**)&ps2,  d_s2);
    cudaGetSymbolAddress((void**)&pA,   d_bufA);
    cudaGetSymbolAddress((void**)&pSt,  d_stats);

    // zero stats + s1 + s2 (each replay)
    zero3_kernel<<<(512 + 2*24576 + 255)/256, 256>>>(
        (float4*)pSt, 512, (float4*)ps1, 24576, (float4*)ps2, 24576);

    // fp16 conversions + relayouts
    cvt_kernel<<<(CVT_TOT4+255)/256, 256>>>(X, W1, e_l0, e_l1, e_l2);
    wt_kernel<<<384, 256>>>(Ws);

    // edge_cat output (independent)
    edge_kernel<<<2048, 256>>>(A, out + ROWS*FF);

    // Wh projection (batched over be) + fused s1/s2 dots
    gemm4_kernel<1><<<dim3(SLOTS/64, NN/64, BE), 256>>>(
        pXH, pWtH, pWh, NN, SLOTS, FF,
        (long)NN*FF, (long)FF*SLOTS, (long)NN*SLOTS, EE, EE,
        1.f, nullptr, 0.f, nullptr, a1, a2, ps1, ps2);

    // fused masked softmax + P@Wh + ELU -> H
    att4_kernel<<<dim3(NN/32, BE), 256>>>(A, pWh, ps1, ps2, pH);

    // H @ W1 * 0.5 + 0.5*X -> bufA, stats0; bn1 -> HnH + HnF
    gemm4_kernel<0><<<dim3(FF/64, ROWS/64, 1), 256>>>(
        pH, pW1H, pA, ROWS, FF, HC, 0,0,0, 1,1,
        0.5f, X, 0.5f, pSt + 0, nullptr, nullptr, nullptr, nullptr);
    norm2_kernel<<<(ROWS*FF/4+255)/256, 256>>>(pA, pHnH, pHnF, pSt + 0, bn1_g, bn1_b, FF, 0);

    // Hn @ e_l0 -> bufA, stats1; elu(bn) -> Z0
    gemm4_kernel<0><<<dim3(L0C/64, ROWS/64, 1), 256>>>(
        pHnH, pL0H, pA, ROWS, L0C, FF, 0,0,0, 1,1,
        1.f, nullptr, 0.f, pSt + 512, nullptr, nullptr, nullptr, nullptr);
    norm2_kernel<<<(ROWS*L0C/4+255)/256, 256>>>(pA, pZ0, nullptr, pSt + 512, e_bn0g, e_bn0b, L0C, 1);

    // Z0 @ e_l1 -> bufA, stats2; elu(bn) -> Z1
    gemm4_kernel<0><<<dim3(L1C/64, ROWS/64, 1), 256>>>(
        pZ0, pL1H, pA, ROWS, L1C, L0C, 0,0,0, 1,1,
        1.f, nullptr, 0.f, pSt + 1024, nullptr, nullptr, nullptr, nullptr);
    norm2_kernel<<<(ROWS*L1C/4+255)/256, 256>>>(pA, pZ1, nullptr, pSt + 1024, e_bn1g, e_bn1b, L1C, 1);

    // Z1 @ e_l2 + HnF -> bufA, stats3; bn2 -> out
    gemm4_kernel<0><<<dim3(FF/64, ROWS/64, 1), 256>>>(
        pZ1, pL2H, pA, ROWS, FF, L1C, 0,0,0, 1,1,
        1.f, pHnF, 1.f, pSt + 1536, nullptr, nullptr, nullptr, nullptr);
    norm2_kernel<<<(ROWS*FF/4+255)/256, 256>>>(pA, nullptr, out, pSt + 1536, bn2_g, bn2_b, FF, 0);
}

// round 8
// speedup vs baseline: 1.8030x; 1.2237x over previous
// GCRN fused pipeline — R8 resubmission of R6/R7 source (infra failed twice;
// trivial header change to perturb source hash). Semantics identical.
#include <cuda_runtime.h>
#include <cuda_fp16.h>
#include <math.h>
#include <stdint.h>

// Problem constants
#define BB 8
#define NN 1024
#define FF 128
#define GG 64
#define MM 4
#define EE 3
#define BE (BB*EE)        // 24
#define SLOTS (MM*GG)     // 256
#define ROWS (BB*NN)      // 8192
#define HC (MM*EE*GG)     // 768
#define L0C 256
#define L1C 256
#define LOG2E 1.44269504f

// ---------------- scratch ----------------
__device__ __half d_XH [ROWS*FF];
__device__ __half d_WtH[EE*FF*SLOTS];
__device__ __half d_W1H[HC*FF];
__device__ __half d_L0H[FF*L0C];
__device__ __half d_L1H[L0C*L1C];
__device__ __half d_L2H[L1C*FF];
__device__ __half d_Wh [BE*NN*SLOTS];        // [be][n][m*64+g]
__device__ __half d_H  [ROWS*HC];            // [b*N+n][m*192+e*64+g]
__device__ __half d_HnH[ROWS*FF];
__device__ float  d_HnF[ROWS*FF];
__device__ __half d_Z0h[ROWS*L0C];
__device__ __half d_Z1h[ROWS*L1C];
__device__ float  d_s1[BE*MM*NN];            // pre-scaled by log2(e)
__device__ float  d_s2[BE*MM*NN];            // pre-scaled by log2(e)
__device__ unsigned short d_pm[BE*NN*64];    // bit-packed mask: [be][i][j/16]
__device__ float  d_bufA[ROWS*L0C];
__device__ float  d_stats[4*512];

// ---------------- helpers ----------------
__device__ __forceinline__ uint32_t smem_u32(const void* p) {
    return (uint32_t)__cvta_generic_to_shared(p);
}
__device__ __forceinline__ void cp16(uint32_t dst, const void* src) {
    asm volatile("cp.async.cg.shared.global [%0], [%1], 16;" :: "r"(dst), "l"(src) : "memory");
}
#define CP_COMMIT asm volatile("cp.async.commit_group;" ::: "memory")
#define CP_WAIT1  asm volatile("cp.async.wait_group 1;" ::: "memory")
#define CP_WAIT0  asm volatile("cp.async.wait_group 0;" ::: "memory")

__device__ __forceinline__ void ldsm_x4(uint32_t* r, uint32_t addr) {
    asm volatile("ldmatrix.sync.aligned.m8n8.x4.shared.b16 {%0,%1,%2,%3}, [%4];"
        : "=r"(r[0]), "=r"(r[1]), "=r"(r[2]), "=r"(r[3]) : "r"(addr));
}
__device__ __forceinline__ void ldsm_x4t(uint32_t* r, uint32_t addr) {
    asm volatile("ldmatrix.sync.aligned.m8n8.x4.trans.shared.b16 {%0,%1,%2,%3}, [%4];"
        : "=r"(r[0]), "=r"(r[1]), "=r"(r[2]), "=r"(r[3]) : "r"(addr));
}
__device__ __forceinline__ void mma_f16(float* d, const uint32_t* a, uint32_t b0, uint32_t b1) {
    asm volatile(
        "mma.sync.aligned.m16n8k16.row.col.f32.f16.f16.f32 "
        "{%0,%1,%2,%3}, {%4,%5,%6,%7}, {%8,%9}, {%0,%1,%2,%3};"
        : "+f"(d[0]), "+f"(d[1]), "+f"(d[2]), "+f"(d[3])
        : "r"(a[0]), "r"(a[1]), "r"(a[2]), "r"(a[3]), "r"(b0), "r"(b1));
}
__device__ __forceinline__ __half2 ex2_h2(__half2 x) {
    uint32_t xi = *(uint32_t*)&x, r;
    asm("ex2.approx.f16x2 %0, %1;" : "=r"(r) : "r"(xi));
    return *(__half2*)&r;
}

// ---------------- tiny utility kernels ----------------
__global__ void zero3_kernel(float4* a, int na, float4* b, int nb, float4* c, int nc) {
    int i = blockIdx.x*blockDim.x + threadIdx.x;
    float4 z = make_float4(0.f,0.f,0.f,0.f);
    if (i < na) a[i] = z;
    else if ((i -= na) < nb) b[i] = z;
    else if ((i -= nb) < nc) c[i] = z;
}

// convert X, W1, e_l0, e_l1, e_l2 to fp16 (vectorized x4)
#define CVT_NX (ROWS*FF)
#define CVT_NW1 (HC*FF)
#define CVT_NL0 (FF*L0C)
#define CVT_NL1 (L0C*L1C)
#define CVT_NL2 (L1C*FF)
#define CVT_TOT4 ((CVT_NX+CVT_NW1+CVT_NL0+CVT_NL1+CVT_NL2)/4)
__global__ void cvt_kernel(const float* __restrict__ X, const float* __restrict__ W1,
                           const float* __restrict__ L0, const float* __restrict__ L1,
                           const float* __restrict__ L2) {
    int i4 = blockIdx.x*blockDim.x + threadIdx.x;
    if (i4 >= CVT_TOT4) return;
    int i = i4*4;
    const float* src; __half* dst;
    if (i < CVT_NX) { src = X; dst = d_XH; }
    else if ((i -= CVT_NX) < CVT_NW1) { src = W1; dst = d_W1H; }
    else if ((i -= CVT_NW1) < CVT_NL0) { src = L0; dst = d_L0H; }
    else if ((i -= CVT_NL0) < CVT_NL1) { src = L1; dst = d_L1H; }
    else { i -= CVT_NL1; src = L2; dst = d_L2H; }
    float4 v = *(const float4*)(src + i);
    __half2 h0 = __floats2half2_rn(v.x, v.y);
    __half2 h1 = __floats2half2_rn(v.z, v.w);
    *(__half2*)(dst + i) = h0;
    *(__half2*)(dst + i + 2) = h1;
}

// WtH[e][f][m*64+g] = (half)Ws[e][(m*128+f)*64+g]
__global__ void wt_kernel(const float* __restrict__ Ws) {
    int idx = blockIdx.x*blockDim.x + threadIdx.x;
    if (idx >= EE*FF*SLOTS) return;
    int e = idx >> 15;
    int r = idx & 32767;
    int f = r >> 8;
    int c = r & 255;
    int m = c >> 6, g = c & 63;
    d_WtH[idx] = __float2half(Ws[e*32768 + m*8192 + f*64 + g]);
}

// edge_cat[b,i,j,e] = (float)A[b,e,i,j] (streaming); also emits bit-packed mask
__global__ void edge_kernel(const int* __restrict__ A, float* __restrict__ out,
                            unsigned short* __restrict__ pm) {
    int idx = blockIdx.x*blockDim.x + threadIdx.x;
    if (idx >= BB*NN*(NN/16)) return;
    int c16 = idx & 63;
    int j0 = c16 << 4;
    int bi = idx >> 6;
    int b = bi >> 10, i = bi & 1023;
    float v[48];
    unsigned bits[3] = {0u, 0u, 0u};
#pragma unroll
    for (int e = 0; e < 3; e++) {
        const int4* src = (const int4*)(A + (((long)(b*3+e)*NN + i) << 10) + j0);
#pragma unroll
        for (int k = 0; k < 4; k++) {
            int4 a = __ldcs(src + k);
            v[(k*4+0)*3+e] = (float)a.x;
            v[(k*4+1)*3+e] = (float)a.y;
            v[(k*4+2)*3+e] = (float)a.z;
            v[(k*4+3)*3+e] = (float)a.w;
            bits[e] |= ((a.x > 0) ? 1u : 0u) << (k*4+0);
            bits[e] |= ((a.y > 0) ? 1u : 0u) << (k*4+1);
            bits[e] |= ((a.z > 0) ? 1u : 0u) << (k*4+2);
            bits[e] |= ((a.w > 0) ? 1u : 0u) << (k*4+3);
        }
    }
    float4* o = (float4*)(out + (long)bi*3072 + (long)j0*3);
#pragma unroll
    for (int k = 0; k < 12; k++) __stcs(o + k, ((float4*)v)[k]);
#pragma unroll
    for (int e = 0; e < 3; e++)
        pm[(((long)(b*3+e))*NN + i)*64 + c16] = (unsigned short)bits[e];
}

// ---------------- gemm4: fp16 x fp16 -> fp32, cp.async 2-stage pipeline ----------------
// 64x64 tile, k-tile 32, 8 warps each 16m x 32n. Optional residual/stats/s1s2-dot fusion.
#define AS_H 40
#define BS_H 72
template <int CH>
__global__ void __launch_bounds__(256) gemm4_kernel(
        const __half* __restrict__ Ah, const __half* __restrict__ Bh, void* __restrict__ Cout,
        int M, int N, int K,
        long sA, long sB, long sC, int zDivA, int zModB,
        float alpha, const float* __restrict__ R, float beta,
        float* __restrict__ stats,
        const float* __restrict__ a1, const float* __restrict__ a2,
        float* __restrict__ s1o, float* __restrict__ s2o) {
    __shared__ __half As[2][64*AS_H];
    __shared__ __half Bs[2][32*BS_H];
    int z = blockIdx.z;
    Ah += (long)(z / zDivA) * sA;
    Bh += (long)(z % zModB) * sB;
    float*  Cf = (float*)Cout + (CH ? 0 : (long)z * sC);
    __half* Ch = (__half*)Cout + (CH ? (long)z * sC : 0);

    int n0 = blockIdx.x * 64, m0 = blockIdx.y * 64;
    int t = threadIdx.x, lane = t & 31, w = t >> 5;
    int gid = lane >> 2, tig = lane & 3;
    int mrow = (w & 3) * 16, ncol = (w >> 2) * 32;
    int l16 = lane & 15, lhi = (lane >> 4) * 8;

    // cp.async chunk positions
    int am_ = t >> 2, akq = (t & 3) * 8;           // A: 1 chunk/thread
    int bkk = t >> 3, bnq = (t & 7) * 8;           // B: 1 chunk/thread
    long aoff = (long)(m0 + am_)*K + akq;
    long boff = (long)bkk*N + n0 + bnq;
    uint32_t adst[2] = { smem_u32(&As[0][am_*AS_H + akq]), smem_u32(&As[1][am_*AS_H + akq]) };
    uint32_t bdst[2] = { smem_u32(&Bs[0][bkk*BS_H + bnq]), smem_u32(&Bs[1][bkk*BS_H + bnq]) };
    uint32_t aA[2] = { smem_u32(&As[0][(mrow+l16)*AS_H + lhi]), smem_u32(&As[1][(mrow+l16)*AS_H + lhi]) };
    uint32_t aB[2] = { smem_u32(&Bs[0][l16*BS_H + ncol + lhi]), smem_u32(&Bs[1][l16*BS_H + ncol + lhi]) };

    float acc[4][4];
#pragma unroll
    for (int nt = 0; nt < 4; nt++)
#pragma unroll
        for (int q = 0; q < 4; q++) acc[nt][q] = 0.f;

    int T = K >> 5;
    // prologue: tile 0 -> stage 0
    cp16(adst[0], Ah + aoff);
    cp16(bdst[0], Bh + boff);
    CP_COMMIT;

    for (int tk = 0; tk < T; tk++) {
        int st = tk & 1;
        __syncthreads();
        if (tk+1 < T) {
            int k0 = (tk+1) << 5;
            cp16(adst[st^1], Ah + aoff + k0);
            cp16(bdst[st^1], Bh + boff + (long)k0*N);
            CP_COMMIT;
            CP_WAIT1;
        } else {
            CP_WAIT0;
        }
        __syncthreads();
#pragma unroll
        for (int ks = 0; ks < 2; ks++) {
            uint32_t af[4];
            ldsm_x4(af, aA[st] + ks*32);
            uint32_t bfr[2][4];
#pragma unroll
            for (int ntp = 0; ntp < 2; ntp++)
                ldsm_x4t(bfr[ntp], aB[st] + (ks*16*BS_H + ntp*16)*2);
#pragma unroll
            for (int nt = 0; nt < 4; nt++)
                mma_f16(acc[nt], af, bfr[nt>>1][(nt&1)*2], bfr[nt>>1][(nt&1)*2+1]);
        }
    }
    // epilogue (fragment layout)
    float stS[4][2], stQ[4][2];
    float d1a = 0.f, d1b = 0.f, d2a = 0.f, d2b = 0.f;
    const float* a1e = a1 ? a1 + (z % 3)*SLOTS : nullptr;
    const float* a2e = a2 ? a2 + (z % 3)*SLOTS : nullptr;
    long r0 = m0 + mrow + gid, r1 = r0 + 8;
#pragma unroll
    for (int nt = 0; nt < 4; nt++) {
        int c = n0 + ncol + nt*8 + 2*tig;
        float v0 = alpha*acc[nt][0], v1 = alpha*acc[nt][1];
        float v2 = alpha*acc[nt][2], v3 = alpha*acc[nt][3];
        if (R) {
            float2 ra = *(const float2*)(R + r0*N + c);
            float2 rb = *(const float2*)(R + r1*N + c);
            v0 += beta*ra.x; v1 += beta*ra.y; v2 += beta*rb.x; v3 += beta*rb.y;
        }
        if (CH) {
            *(__half2*)(Ch + r0*N + c) = __floats2half2_rn(v0, v1);
            *(__half2*)(Ch + r1*N + c) = __floats2half2_rn(v2, v3);
        } else {
            *(float2*)(Cf + r0*N + c) = make_float2(v0, v1);
            *(float2*)(Cf + r1*N + c) = make_float2(v2, v3);
        }
        if (a1e) {
            // pre-scale attention scores by log2(e) for ex2-based softmax
            float w10 = a1e[c]*LOG2E, w11 = a1e[c+1]*LOG2E;
            float w20 = a2e[c]*LOG2E, w21 = a2e[c+1]*LOG2E;
            d1a += v0*w10 + v1*w11; d1b += v2*w10 + v3*w11;
            d2a += v0*w20 + v1*w21; d2b += v2*w20 + v3*w21;
        }
        stS[nt][0] = v0 + v2; stS[nt][1] = v1 + v3;
        stQ[nt][0] = v0*v0 + v2*v2; stQ[nt][1] = v1*v1 + v3*v3;
    }
    if (a1e) {
        d1a += __shfl_down_sync(0xffffffffu, d1a, 1); d1a += __shfl_down_sync(0xffffffffu, d1a, 2);
        d1b += __shfl_down_sync(0xffffffffu, d1b, 1); d1b += __shfl_down_sync(0xffffffffu, d1b, 2);
        d2a += __shfl_down_sync(0xffffffffu, d2a, 1); d2a += __shfl_down_sync(0xffffffffu, d2a, 2);
        d2b += __shfl_down_sync(0xffffffffu, d2b, 1); d2b += __shfl_down_sync(0xffffffffu, d2b, 2);
        if (tig == 0) {
            int mhead = n0 >> 6;
            int base = (z*4 + mhead)*NN;
            atomicAdd(&s1o[base + r0], d1a);
            atomicAdd(&s1o[base + r1], d1b);
            atomicAdd(&s2o[base + r0], d2a);
            atomicAdd(&s2o[base + r1], d2b);
        }
    }
    if (stats) {
#pragma unroll
        for (int nt = 0; nt < 4; nt++) {
#pragma unroll
            for (int cc = 0; cc < 2; cc++) {
                float s = stS[nt][cc], q = stQ[nt][cc];
#pragma unroll
                for (int off = 16; off >= 4; off >>= 1) {
                    s += __shfl_down_sync(0xffffffffu, s, off);
                    q += __shfl_down_sync(0xffffffffu, q, off);
                }
                if (lane < 4) {
                    int col = n0 + ncol + nt*8 + 2*lane + cc;
                    atomicAdd(&stats[col], s);
                    atomicAdd(&stats[N + col], q);
                }
            }
        }
    }
}

// ---------------- attention v5: half2 softmax (ex2.f16x2) + packed mask ----------------
#define SWH_H 264
#define SP_H  40
__global__ void __launch_bounds__(256, 3) att5_kernel(
        const unsigned short* __restrict__ pm, const __half* __restrict__ Wh,
        const float* __restrict__ s1, const float* __restrict__ s2,
        __half* __restrict__ H) {
    __shared__ __half sWh[2][32*SWH_H];
    __shared__ __half sP[4*32*SP_H];
    __shared__ float sDen[1024];
    __shared__ float sDen2[128];

    const int be = blockIdx.y;
    const int b  = be / 3, e = be % 3;
    const int i0 = blockIdx.x * 32;
    const int t  = threadIdx.x;
    const int lane = t & 31;
    const int w  = t >> 5;
    const int gid = lane >> 2, tig = lane & 3;
    const int l16 = lane & 15, lhi = (lane >> 4) * 8;

    const int ip = t >> 3;        // p-phase row 0..31
    const int jg = t & 7;         // p-phase j-chunk of 4
    const int am = w >> 1;        // head
    const int nh = (w & 1) * 32;  // n-half

    const __half2 c001 = __float2half2_rn(0.01f);

    float s1v[4];
#pragma unroll
    for (int m = 0; m < 4; m++) s1v[m] = s1[(be*4+m)*NN + i0 + ip];

    float den[4] = {0.f,0.f,0.f,0.f};
    float acc[2][4][4];
#pragma unroll
    for (int mt = 0; mt < 2; mt++)
#pragma unroll
        for (int nt = 0; nt < 4; nt++)
#pragma unroll
            for (int q = 0; q < 4; q++) acc[mt][nt][q] = 0.f;

    const uint32_t* pmRow = (const uint32_t*)pm + ((long)be*NN + i0 + ip)*32;
    const __half* WhB = Wh + (long)be*NN*SLOTS;
    const float* s2b  = s2 + be*4*NN;

    // cp.async chunk positions: 4 chunks per thread (tile = 1024 x 16B)
    int off[4];
    uint32_t wdst[2][4];
#pragma unroll
    for (int k = 0; k < 4; k++) {
        int idx = t + k*256;
        int jj = idx >> 5, cq = idx & 31;
        off[k] = jj*256 + cq*8;
        wdst[0][k] = smem_u32(&sWh[0][jj*SWH_H + cq*8]);
        wdst[1][k] = smem_u32(&sWh[1][jj*SWH_H + cq*8]);
    }
    uint32_t aP = smem_u32(&sP[(am*32 + l16)*SP_H + lhi]);
    uint32_t aW[2] = { smem_u32(&sWh[0][l16*SWH_H + am*64 + nh + lhi]),
                       smem_u32(&sWh[1][l16*SWH_H + am*64 + nh + lhi]) };

    // prologue: tile 0 -> stage 0
#pragma unroll
    for (int k = 0; k < 4; k++) cp16(wdst[0][k], WhB + off[k]);
    CP_COMMIT;

    for (int jt = 0; jt < 32; jt++) {
        const int j0 = jt << 5;
        const int st = jt & 1;
        __syncthreads();                 // mma(jt-1) complete everywhere
        if (jt+1 < 32) {
            const __half* src = WhB + (long)(j0+32)*SLOTS;
#pragma unroll
            for (int k = 0; k < 4; k++) cp16(wdst[st^1][k], src + off[k]);
            CP_COMMIT;
        }
        // p-phase: masked 2^(lrelu(s1+s2)) in half2, 4 heads x 4 j per thread
        {
            uint32_t nib = pmRow[jt] >> (jg*4);
            __half2 hm01 = __floats2half2_rn((float)(nib & 1u), (float)((nib >> 1) & 1u));
            __half2 hm23 = __floats2half2_rn((float)((nib >> 2) & 1u), (float)((nib >> 3) & 1u));
#pragma unroll
            for (int m = 0; m < 4; m++) {
                float4 s4 = *(const float4*)(s2b + m*NN + j0 + jg*4);
                __half2 x01 = __floats2half2_rn(s1v[m]+s4.x, s1v[m]+s4.y);
                __half2 x23 = __floats2half2_rn(s1v[m]+s4.z, s1v[m]+s4.w);
                x01 = __hmax2(x01, __hmul2(x01, c001));   // leaky relu
                x23 = __hmax2(x23, __hmul2(x23, c001));
                __half2 p01 = __hmul2(ex2_h2(x01), hm01);
                __half2 p23 = __hmul2(ex2_h2(x23), hm23);
                __half2 hp[2] = {p01, p23};
                *(uint2*)&sP[(m*32 + ip)*SP_H + jg*4] = *(uint2*)hp;
                float2 df = __half22float2(__hadd2(p01, p23));
                den[m] += df.x + df.y;
            }
        }
        if (jt+1 < 32) { CP_WAIT1; } else { CP_WAIT0; }
        __syncthreads();                 // sWh[st] + sP visible
        // mma: head am, n-half nh: P[32x32] @ Wh[32x32]
#pragma unroll
        for (int ks = 0; ks < 2; ks++) {
            uint32_t bfr[2][4];
#pragma unroll
            for (int ntp = 0; ntp < 2; ntp++)
                ldsm_x4t(bfr[ntp], aW[st] + (ks*16*SWH_H + ntp*16)*2);
#pragma unroll
            for (int mt = 0; mt < 2; mt++) {
                uint32_t af[4];
                ldsm_x4(af, aP + (mt*16*SP_H + ks*16)*2);
#pragma unroll
                for (int nt = 0; nt < 4; nt++)
                    mma_f16(acc[mt][nt], af, bfr[nt>>1][(nt&1)*2], bfr[nt>>1][(nt&1)*2+1]);
            }
        }
    }
    // denominator reduce
    __syncthreads();
#pragma unroll
    for (int m = 0; m < 4; m++) sDen[(m*32 + ip)*8 + jg] = den[m];
    __syncthreads();
    if (t < 128) {
        float s = 0.f;
#pragma unroll
        for (int r = 0; r < 8; r++) s += sDen[t*8 + r];
        sDen2[t] = 1.f / fmaxf(s, 1e-30f);
    }
    __syncthreads();
    // epilogue: normalize, ELU, store fp16
#pragma unroll
    for (int mt = 0; mt < 2; mt++) {
        int r0 = mt*16 + gid;
        float inv0 = sDen2[am*32 + r0];
        float inv1 = sDen2[am*32 + r0 + 8];
        long row0 = (long)(b*NN) + i0 + r0;
        long row1 = row0 + 8;
#pragma unroll
        for (int nt = 0; nt < 4; nt++) {
            int col = am*192 + e*64 + nh + nt*8 + 2*tig;
            float v0 = acc[mt][nt][0]*inv0, v1 = acc[mt][nt][1]*inv0;
            float v2 = acc[mt][nt][2]*inv1, v3 = acc[mt][nt][3]*inv1;
            v0 = (v0 > 0.f) ? v0 : expm1f(v0);
            v1 = (v1 > 0.f) ? v1 : expm1f(v1);
            v2 = (v2 > 0.f) ? v2 : expm1f(v2);
            v3 = (v3 > 0.f) ? v3 : expm1f(v3);
            *(__half2*)(H + row0*HC + col) = __floats2half2_rn(v0, v1);
            *(__half2*)(H + row1*HC + col) = __floats2half2_rn(v2, v3);
        }
    }
}

// ---------------- batchnorm normalize: fp32 in -> fp16 (+opt fp32) out ----------------
__global__ void norm2_kernel(const float* __restrict__ Y, __half* __restrict__ oh,
                             float* __restrict__ of,
                             const float* __restrict__ stats,
                             const float* __restrict__ g, const float* __restrict__ bb,
                             int N, int elu) {
    int i4 = blockIdx.x*blockDim.x + threadIdx.x;
    if (i4 >= ROWS*N/4) return;
    int i = i4*4;
    int col = i & (N - 1);
    const float invM = 1.f / (float)ROWS;
    float4 y = *(const float4*)(Y + i);
    float4 sm = *(const float4*)(stats + col);
    float4 sq = *(const float4*)(stats + N + col);
    float4 gg = *(const float4*)(g + col);
    float4 bv = *(const float4*)(bb + col);
    float m0 = sm.x*invM, m1 = sm.y*invM, m2 = sm.z*invM, m3 = sm.w*invM;
    float w0 = gg.x * rsqrtf(sq.x*invM - m0*m0 + 1e-5f);
    float w1 = gg.y * rsqrtf(sq.y*invM - m1*m1 + 1e-5f);
    float w2 = gg.z * rsqrtf(sq.z*invM - m2*m2 + 1e-5f);
    float w3 = gg.w * rsqrtf(sq.w*invM - m3*m3 + 1e-5f);
    float v0 = (y.x - m0)*w0 + bv.x;
    float v1 = (y.y - m1)*w1 + bv.y;
    float v2 = (y.z - m2)*w2 + bv.z;
    float v3 = (y.w - m3)*w3 + bv.w;
    if (elu) {
        v0 = (v0 > 0.f) ? v0 : expm1f(v0);
        v1 = (v1 > 0.f) ? v1 : expm1f(v1);
        v2 = (v2 > 0.f) ? v2 : expm1f(v2);
        v3 = (v3 > 0.f) ? v3 : expm1f(v3);
    }
    if (oh) {
        *(__half2*)(oh + i)     = __floats2half2_rn(v0, v1);
        *(__half2*)(oh + i + 2) = __floats2half2_rn(v2, v3);
    }
    if (of) *(float4*)(of + i) = make_float4(v0, v1, v2, v3);
}

// ---------------- launch ----------------
extern "C" void kernel_launch(void* const* d_in, const int* in_sizes, int n_in,
                              void* d_out, int out_size) {
    const int*   A      = (const int*)  d_in[0];
    const float* X      = (const float*)d_in[1];
    const float* Ws     = (const float*)d_in[3];
    const float* a1     = (const float*)d_in[4];
    const float* a2     = (const float*)d_in[5];
    const float* W1     = (const float*)d_in[6];
    const float* bn1_g  = (const float*)d_in[7];
    const float* bn1_b  = (const float*)d_in[8];
    const float* e_l0   = (const float*)d_in[9];
    const float* e_bn0g = (const float*)d_in[10];
    const float* e_bn0b = (const float*)d_in[11];
    const float* e_l1   = (const float*)d_in[12];
    const float* e_bn1g = (const float*)d_in[13];
    const float* e_bn1b = (const float*)d_in[14];
    const float* e_l2   = (const float*)d_in[15];
    const float* bn2_g  = (const float*)d_in[16];
    const float* bn2_b  = (const float*)d_in[17];
    float* out = (float*)d_out;

    float *ps1, *ps2, *pHnF, *pA, *pSt;
    __half *pXH, *pWtH, *pW1H, *pL0H, *pL1H, *pL2H, *pWh, *pH, *pHnH, *pZ0, *pZ1;
    unsigned short* ppm;
    cudaGetSymbolAddress((void**)&pXH,  d_XH);
    cudaGetSymbolAddress((void**)&pWtH, d_WtH);
    cudaGetSymbolAddress((void**)&pW1H, d_W1H);
    cudaGetSymbolAddress((void**)&pL0H, d_L0H);
    cudaGetSymbolAddress((void**)&pL1H, d_L1H);
    cudaGetSymbolAddress((void**)&pL2H, d_L2H);
    cudaGetSymbolAddress((void**)&pWh,  d_Wh);
    cudaGetSymbolAddress((void**)&pH,   d_H);
    cudaGetSymbolAddress((void**)&pHnH, d_HnH);
    cudaGetSymbolAddress((void**)&pHnF, d_HnF);
    cudaGetSymbolAddress((void**)&pZ0,  d_Z0h);
    cudaGetSymbolAddress((void**)&pZ1,  d_Z1h);
    cudaGetSymbolAddress((void**)&ps1,  d_s1);
    cudaGetSymbolAddress((void**)&ps2,  d_s2);
    cudaGetSymbolAddress((void**)&ppm,  d_pm);
    cudaGetSymbolAddress((void**)&pA,   d_bufA);
    cudaGetSymbolAddress((void**)&pSt,  d_stats);

    // zero stats + s1 + s2 (each replay)
    zero3_kernel<<<(512 + 2*24576 + 255)/256, 256>>>(
        (float4*)pSt, 512, (float4*)ps1, 24576, (float4*)ps2, 24576);

    // fp16 conversions + relayouts
    cvt_kernel<<<(CVT_TOT4+255)/256, 256>>>(X, W1, e_l0, e_l1, e_l2);
    wt_kernel<<<384, 256>>>(Ws);

    // edge_cat output + packed mask
    edge_kernel<<<2048, 256>>>(A, out + ROWS*FF, ppm);

    // Wh projection (batched over be) + fused s1/s2 dots (log2e-scaled)
    gemm4_kernel<1><<<dim3(SLOTS/64, NN/64, BE), 256>>>(
        pXH, pWtH, pWh, NN, SLOTS, FF,
        (long)NN*FF, (long)FF*SLOTS, (long)NN*SLOTS, EE, EE,
        1.f, nullptr, 0.f, nullptr, a1, a2, ps1, ps2);

    // fused masked softmax + P@Wh + ELU -> H
    att5_kernel<<<dim3(NN/32, BE), 256>>>(ppm, pWh, ps1, ps2, pH);

    // H @ W1 * 0.5 + 0.5*X -> bufA, stats0; bn1 -> HnH + HnF
    gemm4_kernel<0><<<dim3(FF/64, ROWS/64, 1), 256>>>(
        pH, pW1H, pA, ROWS, FF, HC, 0,0,0, 1,1,
        0.5f, X, 0.5f, pSt + 0, nullptr, nullptr, nullptr, nullptr);
    norm2_kernel<<<(ROWS*FF/4+255)/256, 256>>>(pA, pHnH, pHnF, pSt + 0, bn1_g, bn1_b, FF, 0);

    // Hn @ e_l0 -> bufA, stats1; elu(bn) -> Z0
    gemm4_kernel<0><<<dim3(L0C/64, ROWS/64, 1), 256>>>(
        pHnH, pL0H, pA, ROWS, L0C, FF, 0,0,0, 1,1,
        1.f, nullptr, 0.f, pSt + 512, nullptr, nullptr, nullptr, nullptr);
    norm2_kernel<<<(ROWS*L0C/4+255)/256, 256>>>(pA, pZ0, nullptr, pSt + 512, e_bn0g, e_bn0b, L0C, 1);

    // Z0 @ e_l1 -> bufA, stats2; elu(bn) -> Z1
    gemm4_kernel<0><<<dim3(L1C/64, ROWS/64, 1), 256>>>(
        pZ0, pL1H, pA, ROWS, L1C, L0C, 0,0,0, 1,1,
        1.f, nullptr, 0.f, pSt + 1024, nullptr, nullptr, nullptr, nullptr);
    norm2_kernel<<<(ROWS*L1C/4+255)/256, 256>>>(pA, pZ1, nullptr, pSt + 1024, e_bn1g, e_bn1b, L1C, 1);

    // Z1 @ e_l2 + HnF -> bufA, stats3; bn2 -> out
    gemm4_kernel<0><<<dim3(FF/64, ROWS/64, 1), 256>>>(
        pZ1, pL2H, pA, ROWS, FF, L1C, 0,0,0, 1,1,
        1.f, pHnF, 1.f, pSt + 1536, nullptr, nullptr, nullptr, nullptr);
    norm2_kernel<<<(ROWS*FF/4+255)/256, 256>>>(pA, nullptr, out, pSt + 1536, bn2_g, bn2_b, FF, 0);
}

// round 9
// speedup vs baseline: 1.8593x; 1.0312x over previous
// GCRN fused pipeline — R9: stream-forked edge overlap + coalesced edge v2.
#include <cuda_runtime.h>
#include <cuda_fp16.h>
#include <math.h>
#include <stdint.h>

// Problem constants
#define BB 8
#define NN 1024
#define FF 128
#define GG 64
#define MM 4
#define EE 3
#define BE (BB*EE)        // 24
#define SLOTS (MM*GG)     // 256
#define ROWS (BB*NN)      // 8192
#define HC (MM*EE*GG)     // 768
#define L0C 256
#define L1C 256
#define LOG2E 1.44269504f

// ---------------- scratch ----------------
__device__ __half d_XH [ROWS*FF];
__device__ __half d_WtH[EE*FF*SLOTS];
__device__ __half d_W1H[HC*FF];
__device__ __half d_L0H[FF*L0C];
__device__ __half d_L1H[L0C*L1C];
__device__ __half d_L2H[L1C*FF];
__device__ __half d_Wh [BE*NN*SLOTS];        // [be][n][m*64+g]
__device__ __half d_H  [ROWS*HC];            // [b*N+n][m*192+e*64+g]
__device__ __half d_HnH[ROWS*FF];
__device__ float  d_HnF[ROWS*FF];
__device__ __half d_Z0h[ROWS*L0C];
__device__ __half d_Z1h[ROWS*L1C];
__device__ float  d_s1[BE*MM*NN];            // pre-scaled by log2(e)
__device__ float  d_s2[BE*MM*NN];            // pre-scaled by log2(e)
__device__ unsigned short d_pm[BE*NN*64];    // bit-packed mask: [be][i][j/16]
__device__ float  d_bufA[ROWS*L0C];
__device__ float  d_stats[4*512];

// ---------------- helpers ----------------
__device__ __forceinline__ uint32_t smem_u32(const void* p) {
    return (uint32_t)__cvta_generic_to_shared(p);
}
__device__ __forceinline__ void cp16(uint32_t dst, const void* src) {
    asm volatile("cp.async.cg.shared.global [%0], [%1], 16;" :: "r"(dst), "l"(src) : "memory");
}
#define CP_COMMIT asm volatile("cp.async.commit_group;" ::: "memory")
#define CP_WAIT1  asm volatile("cp.async.wait_group 1;" ::: "memory")
#define CP_WAIT0  asm volatile("cp.async.wait_group 0;" ::: "memory")

__device__ __forceinline__ void ldsm_x4(uint32_t* r, uint32_t addr) {
    asm volatile("ldmatrix.sync.aligned.m8n8.x4.shared.b16 {%0,%1,%2,%3}, [%4];"
        : "=r"(r[0]), "=r"(r[1]), "=r"(r[2]), "=r"(r[3]) : "r"(addr));
}
__device__ __forceinline__ void ldsm_x4t(uint32_t* r, uint32_t addr) {
    asm volatile("ldmatrix.sync.aligned.m8n8.x4.trans.shared.b16 {%0,%1,%2,%3}, [%4];"
        : "=r"(r[0]), "=r"(r[1]), "=r"(r[2]), "=r"(r[3]) : "r"(addr));
}
__device__ __forceinline__ void mma_f16(float* d, const uint32_t* a, uint32_t b0, uint32_t b1) {
    asm volatile(
        "mma.sync.aligned.m16n8k16.row.col.f32.f16.f16.f32 "
        "{%0,%1,%2,%3}, {%4,%5,%6,%7}, {%8,%9}, {%0,%1,%2,%3};"
        : "+f"(d[0]), "+f"(d[1]), "+f"(d[2]), "+f"(d[3])
        : "r"(a[0]), "r"(a[1]), "r"(a[2]), "r"(a[3]), "r"(b0), "r"(b1));
}
__device__ __forceinline__ __half2 ex2_h2(__half2 x) {
    uint32_t xi = *(uint32_t*)&x, r;
    asm("ex2.approx.f16x2 %0, %1;" : "=r"(r) : "r"(xi));
    return *(__half2*)&r;
}

// ---------------- tiny utility kernels ----------------
__global__ void zero3_kernel(float4* a, int na, float4* b, int nb, float4* c, int nc) {
    int i = blockIdx.x*blockDim.x + threadIdx.x;
    float4 z = make_float4(0.f,0.f,0.f,0.f);
    if (i < na) a[i] = z;
    else if ((i -= na) < nb) b[i] = z;
    else if ((i -= nb) < nc) c[i] = z;
}

// convert X, W1, e_l0, e_l1, e_l2 to fp16 (vectorized x4)
#define CVT_NX (ROWS*FF)
#define CVT_NW1 (HC*FF)
#define CVT_NL0 (FF*L0C)
#define CVT_NL1 (L0C*L1C)
#define CVT_NL2 (L1C*FF)
#define CVT_TOT4 ((CVT_NX+CVT_NW1+CVT_NL0+CVT_NL1+CVT_NL2)/4)
__global__ void cvt_kernel(const float* __restrict__ X, const float* __restrict__ W1,
                           const float* __restrict__ L0, const float* __restrict__ L1,
                           const float* __restrict__ L2) {
    int i4 = blockIdx.x*blockDim.x + threadIdx.x;
    if (i4 >= CVT_TOT4) return;
    int i = i4*4;
    const float* src; __half* dst;
    if (i < CVT_NX) { src = X; dst = d_XH; }
    else if ((i -= CVT_NX) < CVT_NW1) { src = W1; dst = d_W1H; }
    else if ((i -= CVT_NW1) < CVT_NL0) { src = L0; dst = d_L0H; }
    else if ((i -= CVT_NL0) < CVT_NL1) { src = L1; dst = d_L1H; }
    else { i -= CVT_NL1; src = L2; dst = d_L2H; }
    float4 v = *(const float4*)(src + i);
    __half2 h0 = __floats2half2_rn(v.x, v.y);
    __half2 h1 = __floats2half2_rn(v.z, v.w);
    *(__half2*)(dst + i) = h0;
    *(__half2*)(dst + i + 2) = h1;
}

// WtH[e][f][m*64+g] = (half)Ws[e][(m*128+f)*64+g]
__global__ void wt_kernel(const float* __restrict__ Ws) {
    int idx = blockIdx.x*blockDim.x + threadIdx.x;
    if (idx >= EE*FF*SLOTS) return;
    int e = idx >> 15;
    int r = idx & 32767;
    int f = r >> 8;
    int c = r & 255;
    int m = c >> 6, g = c & 63;
    d_WtH[idx] = __float2half(Ws[e*32768 + m*8192 + f*64 + g]);
}

// edge v2: one block per (b,i) row; smem transpose for perfectly coalesced stores.
// Also emits bit-packed mask via ballot.
__global__ void __launch_bounds__(256) edge2_kernel(
        const int* __restrict__ A, float* __restrict__ out,
        unsigned short* __restrict__ pm) {
    __shared__ float sv[3072];
    int bi = blockIdx.x;            // b*N + i
    int b = bi >> 10, i = bi & 1023;
    int t = threadIdx.x;
    int lane = t & 31, w = t >> 5;  // warp 0..7
#pragma unroll
    for (int e = 0; e < 3; e++) {
        const int* src = A + (((long)(b*3+e) << 10) + i)*1024;
        uint32_t* pmW = (uint32_t*)pm + (((long)(b*3+e) << 10) + i)*32;
#pragma unroll
        for (int k = 0; k < 4; k++) {
            int j = t + k*256;
            int a = __ldcs(src + j);
            sv[j*3 + e] = (float)a;
            unsigned bal = __ballot_sync(0xffffffffu, a > 0);
            if (lane == 0) pmW[k*8 + w] = bal;
        }
    }
    __syncthreads();
    float4* o = (float4*)(out + (long)bi*3072);
    const float4* s4 = (const float4*)sv;
#pragma unroll
    for (int k = 0; k < 3; k++) __stcs(o + t + k*256, s4[t + k*256]);
}

// ---------------- gemm4: fp16 x fp16 -> fp32, cp.async 2-stage pipeline ----------------
// 64x64 tile, k-tile 32, 8 warps each 16m x 32n. Optional residual/stats/s1s2-dot fusion.
#define AS_H 40
#define BS_H 72
template <int CH>
__global__ void __launch_bounds__(256) gemm4_kernel(
        const __half* __restrict__ Ah, const __half* __restrict__ Bh, void* __restrict__ Cout,
        int M, int N, int K,
        long sA, long sB, long sC, int zDivA, int zModB,
        float alpha, const float* __restrict__ R, float beta,
        float* __restrict__ stats,
        const float* __restrict__ a1, const float* __restrict__ a2,
        float* __restrict__ s1o, float* __restrict__ s2o) {
    __shared__ __half As[2][64*AS_H];
    __shared__ __half Bs[2][32*BS_H];
    int z = blockIdx.z;
    Ah += (long)(z / zDivA) * sA;
    Bh += (long)(z % zModB) * sB;
    float*  Cf = (float*)Cout + (CH ? 0 : (long)z * sC);
    __half* Ch = (__half*)Cout + (CH ? (long)z * sC : 0);

    int n0 = blockIdx.x * 64, m0 = blockIdx.y * 64;
    int t = threadIdx.x, lane = t & 31, w = t >> 5;
    int gid = lane >> 2, tig = lane & 3;
    int mrow = (w & 3) * 16, ncol = (w >> 2) * 32;
    int l16 = lane & 15, lhi = (lane >> 4) * 8;

    // cp.async chunk positions
    int am_ = t >> 2, akq = (t & 3) * 8;           // A: 1 chunk/thread
    int bkk = t >> 3, bnq = (t & 7) * 8;           // B: 1 chunk/thread
    long aoff = (long)(m0 + am_)*K + akq;
    long boff = (long)bkk*N + n0 + bnq;
    uint32_t adst[2] = { smem_u32(&As[0][am_*AS_H + akq]), smem_u32(&As[1][am_*AS_H + akq]) };
    uint32_t bdst[2] = { smem_u32(&Bs[0][bkk*BS_H + bnq]), smem_u32(&Bs[1][bkk*BS_H + bnq]) };
    uint32_t aA[2] = { smem_u32(&As[0][(mrow+l16)*AS_H + lhi]), smem_u32(&As[1][(mrow+l16)*AS_H + lhi]) };
    uint32_t aB[2] = { smem_u32(&Bs[0][l16*BS_H + ncol + lhi]), smem_u32(&Bs[1][l16*BS_H + ncol + lhi]) };

    float acc[4][4];
#pragma unroll
    for (int nt = 0; nt < 4; nt++)
#pragma unroll
        for (int q = 0; q < 4; q++) acc[nt][q] = 0.f;

    int T = K >> 5;
    // prologue: tile 0 -> stage 0
    cp16(adst[0], Ah + aoff);
    cp16(bdst[0], Bh + boff);
    CP_COMMIT;

    for (int tk = 0; tk < T; tk++) {
        int st = tk & 1;
        __syncthreads();
        if (tk+1 < T) {
            int k0 = (tk+1) << 5;
            cp16(adst[st^1], Ah + aoff + k0);
            cp16(bdst[st^1], Bh + boff + (long)k0*N);
            CP_COMMIT;
            CP_WAIT1;
        } else {
            CP_WAIT0;
        }
        __syncthreads();
#pragma unroll
        for (int ks = 0; ks < 2; ks++) {
            uint32_t af[4];
            ldsm_x4(af, aA[st] + ks*32);
            uint32_t bfr[2][4];
#pragma unroll
            for (int ntp = 0; ntp < 2; ntp++)
                ldsm_x4t(bfr[ntp], aB[st] + (ks*16*BS_H + ntp*16)*2);
#pragma unroll
            for (int nt = 0; nt < 4; nt++)
                mma_f16(acc[nt], af, bfr[nt>>1][(nt&1)*2], bfr[nt>>1][(nt&1)*2+1]);
        }
    }
    // epilogue (fragment layout)
    float stS[4][2], stQ[4][2];
    float d1a = 0.f, d1b = 0.f, d2a = 0.f, d2b = 0.f;
    const float* a1e = a1 ? a1 + (z % 3)*SLOTS : nullptr;
    const float* a2e = a2 ? a2 + (z % 3)*SLOTS : nullptr;
    long r0 = m0 + mrow + gid, r1 = r0 + 8;
#pragma unroll
    for (int nt = 0; nt < 4; nt++) {
        int c = n0 + ncol + nt*8 + 2*tig;
        float v0 = alpha*acc[nt][0], v1 = alpha*acc[nt][1];
        float v2 = alpha*acc[nt][2], v3 = alpha*acc[nt][3];
        if (R) {
            float2 ra = *(const float2*)(R + r0*N + c);
            float2 rb = *(const float2*)(R + r1*N + c);
            v0 += beta*ra.x; v1 += beta*ra.y; v2 += beta*rb.x; v3 += beta*rb.y;
        }
        if (CH) {
            *(__half2*)(Ch + r0*N + c) = __floats2half2_rn(v0, v1);
            *(__half2*)(Ch + r1*N + c) = __floats2half2_rn(v2, v3);
        } else {
            *(float2*)(Cf + r0*N + c) = make_float2(v0, v1);
            *(float2*)(Cf + r1*N + c) = make_float2(v2, v3);
        }
        if (a1e) {
            // pre-scale attention scores by log2(e) for ex2-based softmax
            float w10 = a1e[c]*LOG2E, w11 = a1e[c+1]*LOG2E;
            float w20 = a2e[c]*LOG2E, w21 = a2e[c+1]*LOG2E;
            d1a += v0*w10 + v1*w11; d1b += v2*w10 + v3*w11;
            d2a += v0*w20 + v1*w21; d2b += v2*w20 + v3*w21;
        }
        stS[nt][0] = v0 + v2; stS[nt][1] = v1 + v3;
        stQ[nt][0] = v0*v0 + v2*v2; stQ[nt][1] = v1*v1 + v3*v3;
    }
    if (a1e) {
        d1a += __shfl_down_sync(0xffffffffu, d1a, 1); d1a += __shfl_down_sync(0xffffffffu, d1a, 2);
        d1b += __shfl_down_sync(0xffffffffu, d1b, 1); d1b += __shfl_down_sync(0xffffffffu, d1b, 2);
        d2a += __shfl_down_sync(0xffffffffu, d2a, 1); d2a += __shfl_down_sync(0xffffffffu, d2a, 2);
        d2b += __shfl_down_sync(0xffffffffu, d2b, 1); d2b += __shfl_down_sync(0xffffffffu, d2b, 2);
        if (tig == 0) {
            int mhead = n0 >> 6;
            int base = (z*4 + mhead)*NN;
            atomicAdd(&s1o[base + r0], d1a);
            atomicAdd(&s1o[base + r1], d1b);
            atomicAdd(&s2o[base + r0], d2a);
            atomicAdd(&s2o[base + r1], d2b);
        }
    }
    if (stats) {
#pragma unroll
        for (int nt = 0; nt < 4; nt++) {
#pragma unroll
            for (int cc = 0; cc < 2; cc++) {
                float s = stS[nt][cc], q = stQ[nt][cc];
#pragma unroll
                for (int off = 16; off >= 4; off >>= 1) {
                    s += __shfl_down_sync(0xffffffffu, s, off);
                    q += __shfl_down_sync(0xffffffffu, q, off);
                }
                if (lane < 4) {
                    int col = n0 + ncol + nt*8 + 2*lane + cc;
                    atomicAdd(&stats[col], s);
                    atomicAdd(&stats[N + col], q);
                }
            }
        }
    }
}

// ---------------- attention v5: half2 softmax (ex2.f16x2) + packed mask ----------------
#define SWH_H 264
#define SP_H  40
__global__ void __launch_bounds__(256, 3) att5_kernel(
        const unsigned short* __restrict__ pm, const __half* __restrict__ Wh,
        const float* __restrict__ s1, const float* __restrict__ s2,
        __half* __restrict__ H) {
    __shared__ __half sWh[2][32*SWH_H];
    __shared__ __half sP[4*32*SP_H];
    __shared__ float sDen[1024];
    __shared__ float sDen2[128];

    const int be = blockIdx.y;
    const int b  = be / 3, e = be % 3;
    const int i0 = blockIdx.x * 32;
    const int t  = threadIdx.x;
    const int lane = t & 31;
    const int w  = t >> 5;
    const int gid = lane >> 2, tig = lane & 3;
    const int l16 = lane & 15, lhi = (lane >> 4) * 8;

    const int ip = t >> 3;        // p-phase row 0..31
    const int jg = t & 7;         // p-phase j-chunk of 4
    const int am = w >> 1;        // head
    const int nh = (w & 1) * 32;  // n-half

    const __half2 c001 = __float2half2_rn(0.01f);

    float s1v[4];
#pragma unroll
    for (int m = 0; m < 4; m++) s1v[m] = s1[(be*4+m)*NN + i0 + ip];

    float den[4] = {0.f,0.f,0.f,0.f};
    float acc[2][4][4];
#pragma unroll
    for (int mt = 0; mt < 2; mt++)
#pragma unroll
        for (int nt = 0; nt < 4; nt++)
#pragma unroll
            for (int q = 0; q < 4; q++) acc[mt][nt][q] = 0.f;

    const uint32_t* pmRow = (const uint32_t*)pm + ((long)be*NN + i0 + ip)*32;
    const __half* WhB = Wh + (long)be*NN*SLOTS;
    const float* s2b  = s2 + be*4*NN;

    // cp.async chunk positions: 4 chunks per thread (tile = 1024 x 16B)
    int off[4];
    uint32_t wdst[2][4];
#pragma unroll
    for (int k = 0; k < 4; k++) {
        int idx = t + k*256;
        int jj = idx >> 5, cq = idx & 31;
        off[k] = jj*256 + cq*8;
        wdst[0][k] = smem_u32(&sWh[0][jj*SWH_H + cq*8]);
        wdst[1][k] = smem_u32(&sWh[1][jj*SWH_H + cq*8]);
    }
    uint32_t aP = smem_u32(&sP[(am*32 + l16)*SP_H + lhi]);
    uint32_t aW[2] = { smem_u32(&sWh[0][l16*SWH_H + am*64 + nh + lhi]),
                       smem_u32(&sWh[1][l16*SWH_H + am*64 + nh + lhi]) };

    // prologue: tile 0 -> stage 0
#pragma unroll
    for (int k = 0; k < 4; k++) cp16(wdst[0][k], WhB + off[k]);
    CP_COMMIT;

    for (int jt = 0; jt < 32; jt++) {
        const int j0 = jt << 5;
        const int st = jt & 1;
        __syncthreads();                 // mma(jt-1) complete everywhere
        if (jt+1 < 32) {
            const __half* src = WhB + (long)(j0+32)*SLOTS;
#pragma unroll
            for (int k = 0; k < 4; k++) cp16(wdst[st^1][k], src + off[k]);
            CP_COMMIT;
        }
        // p-phase: masked 2^(lrelu(s1+s2)) in half2, 4 heads x 4 j per thread
        {
            uint32_t nib = pmRow[jt] >> (jg*4);
            __half2 hm01 = __floats2half2_rn((float)(nib & 1u), (float)((nib >> 1) & 1u));
            __half2 hm23 = __floats2half2_rn((float)((nib >> 2) & 1u), (float)((nib >> 3) & 1u));
#pragma unroll
            for (int m = 0; m < 4; m++) {
                float4 s4 = *(const float4*)(s2b + m*NN + j0 + jg*4);
                __half2 x01 = __floats2half2_rn(s1v[m]+s4.x, s1v[m]+s4.y);
                __half2 x23 = __floats2half2_rn(s1v[m]+s4.z, s1v[m]+s4.w);
                x01 = __hmax2(x01, __hmul2(x01, c001));   // leaky relu
                x23 = __hmax2(x23, __hmul2(x23, c001));
                __half2 p01 = __hmul2(ex2_h2(x01), hm01);
                __half2 p23 = __hmul2(ex2_h2(x23), hm23);
                __half2 hp[2] = {p01, p23};
                *(uint2*)&sP[(m*32 + ip)*SP_H + jg*4] = *(uint2*)hp;
                float2 df = __half22float2(__hadd2(p01, p23));
                den[m] += df.x + df.y;
            }
        }
        if (jt+1 < 32) { CP_WAIT1; } else { CP_WAIT0; }
        __syncthreads();                 // sWh[st] + sP visible
        // mma: head am, n-half nh: P[32x32] @ Wh[32x32]
#pragma unroll
        for (int ks = 0; ks < 2; ks++) {
            uint32_t bfr[2][4];
#pragma unroll
            for (int ntp = 0; ntp < 2; ntp++)
                ldsm_x4t(bfr[ntp], aW[st] + (ks*16*SWH_H + ntp*16)*2);
#pragma unroll
            for (int mt = 0; mt < 2; mt++) {
                uint32_t af[4];
                ldsm_x4(af, aP + (mt*16*SP_H + ks*16)*2);
#pragma unroll
                for (int nt = 0; nt < 4; nt++)
                    mma_f16(acc[mt][nt], af, bfr[nt>>1][(nt&1)*2], bfr[nt>>1][(nt&1)*2+1]);
            }
        }
    }
    // denominator reduce
    __syncthreads();
#pragma unroll
    for (int m = 0; m < 4; m++) sDen[(m*32 + ip)*8 + jg] = den[m];
    __syncthreads();
    if (t < 128) {
        float s = 0.f;
#pragma unroll
        for (int r = 0; r < 8; r++) s += sDen[t*8 + r];
        sDen2[t] = 1.f / fmaxf(s, 1e-30f);
    }
    __syncthreads();
    // epilogue: normalize, ELU, store fp16
#pragma unroll
    for (int mt = 0; mt < 2; mt++) {
        int r0 = mt*16 + gid;
        float inv0 = sDen2[am*32 + r0];
        float inv1 = sDen2[am*32 + r0 + 8];
        long row0 = (long)(b*NN) + i0 + r0;
        long row1 = row0 + 8;
#pragma unroll
        for (int nt = 0; nt < 4; nt++) {
            int col = am*192 + e*64 + nh + nt*8 + 2*tig;
            float v0 = acc[mt][nt][0]*inv0, v1 = acc[mt][nt][1]*inv0;
            float v2 = acc[mt][nt][2]*inv1, v3 = acc[mt][nt][3]*inv1;
            v0 = (v0 > 0.f) ? v0 : expm1f(v0);
            v1 = (v1 > 0.f) ? v1 : expm1f(v1);
            v2 = (v2 > 0.f) ? v2 : expm1f(v2);
            v3 = (v3 > 0.f) ? v3 : expm1f(v3);
            *(__half2*)(H + row0*HC + col) = __floats2half2_rn(v0, v1);
            *(__half2*)(H + row1*HC + col) = __floats2half2_rn(v2, v3);
        }
    }
}

// ---------------- batchnorm normalize: fp32 in -> fp16 (+opt fp32) out ----------------
__global__ void norm2_kernel(const float* __restrict__ Y, __half* __restrict__ oh,
                             float* __restrict__ of,
                             const float* __restrict__ stats,
                             const float* __restrict__ g, const float* __restrict__ bb,
                             int N, int elu) {
    int i4 = blockIdx.x*blockDim.x + threadIdx.x;
    if (i4 >= ROWS*N/4) return;
    int i = i4*4;
    int col = i & (N - 1);
    const float invM = 1.f / (float)ROWS;
    float4 y = *(const float4*)(Y + i);
    float4 sm = *(const float4*)(stats + col);
    float4 sq = *(const float4*)(stats + N + col);
    float4 gg = *(const float4*)(g + col);
    float4 bv = *(const float4*)(bb + col);
    float m0 = sm.x*invM, m1 = sm.y*invM, m2 = sm.z*invM, m3 = sm.w*invM;
    float w0 = gg.x * rsqrtf(sq.x*invM - m0*m0 + 1e-5f);
    float w1 = gg.y * rsqrtf(sq.y*invM - m1*m1 + 1e-5f);
    float w2 = gg.z * rsqrtf(sq.z*invM - m2*m2 + 1e-5f);
    float w3 = gg.w * rsqrtf(sq.w*invM - m3*m3 + 1e-5f);
    float v0 = (y.x - m0)*w0 + bv.x;
    float v1 = (y.y - m1)*w1 + bv.y;
    float v2 = (y.z - m2)*w2 + bv.z;
    float v3 = (y.w - m3)*w3 + bv.w;
    if (elu) {
        v0 = (v0 > 0.f) ? v0 : expm1f(v0);
        v1 = (v1 > 0.f) ? v1 : expm1f(v1);
        v2 = (v2 > 0.f) ? v2 : expm1f(v2);
        v3 = (v3 > 0.f) ? v3 : expm1f(v3);
    }
    if (oh) {
        *(__half2*)(oh + i)     = __floats2half2_rn(v0, v1);
        *(__half2*)(oh + i + 2) = __floats2half2_rn(v2, v3);
    }
    if (of) *(float4*)(of + i) = make_float4(v0, v1, v2, v3);
}

// ---------------- launch ----------------
extern "C" void kernel_launch(void* const* d_in, const int* in_sizes, int n_in,
                              void* d_out, int out_size) {
    const int*   A      = (const int*)  d_in[0];
    const float* X      = (const float*)d_in[1];
    const float* Ws     = (const float*)d_in[3];
    const float* a1     = (const float*)d_in[4];
    const float* a2     = (const float*)d_in[5];
    const float* W1     = (const float*)d_in[6];
    const float* bn1_g  = (const float*)d_in[7];
    const float* bn1_b  = (const float*)d_in[8];
    const float* e_l0   = (const float*)d_in[9];
    const float* e_bn0g = (const float*)d_in[10];
    const float* e_bn0b = (const float*)d_in[11];
    const float* e_l1   = (const float*)d_in[12];
    const float* e_bn1g = (const float*)d_in[13];
    const float* e_bn1b = (const float*)d_in[14];
    const float* e_l2   = (const float*)d_in[15];
    const float* bn2_g  = (const float*)d_in[16];
    const float* bn2_b  = (const float*)d_in[17];
    float* out = (float*)d_out;

    float *ps1, *ps2, *pHnF, *pA, *pSt;
    __half *pXH, *pWtH, *pW1H, *pL0H, *pL1H, *pL2H, *pWh, *pH, *pHnH, *pZ0, *pZ1;
    unsigned short* ppm;
    cudaGetSymbolAddress((void**)&pXH,  d_XH);
    cudaGetSymbolAddress((void**)&pWtH, d_WtH);
    cudaGetSymbolAddress((void**)&pW1H, d_W1H);
    cudaGetSymbolAddress((void**)&pL0H, d_L0H);
    cudaGetSymbolAddress((void**)&pL1H, d_L1H);
    cudaGetSymbolAddress((void**)&pL2H, d_L2H);
    cudaGetSymbolAddress((void**)&pWh,  d_Wh);
    cudaGetSymbolAddress((void**)&pH,   d_H);
    cudaGetSymbolAddress((void**)&pHnH, d_HnH);
    cudaGetSymbolAddress((void**)&pHnF, d_HnF);
    cudaGetSymbolAddress((void**)&pZ0,  d_Z0h);
    cudaGetSymbolAddress((void**)&pZ1,  d_Z1h);
    cudaGetSymbolAddress((void**)&ps1,  d_s1);
    cudaGetSymbolAddress((void**)&ps2,  d_s2);
    cudaGetSymbolAddress((void**)&ppm,  d_pm);
    cudaGetSymbolAddress((void**)&pA,   d_bufA);
    cudaGetSymbolAddress((void**)&pSt,  d_stats);

    // Lazy one-time stream/event handles. Device work per call is identical —
    // these only enable a parallel branch in the captured graph.
    static cudaStream_t s2str = nullptr;
    static cudaEvent_t evFork = nullptr, evJoin = nullptr;
    if (!s2str) {
        cudaStreamCreateWithFlags(&s2str, cudaStreamNonBlocking);
        cudaEventCreateWithFlags(&evFork, cudaEventDisableTiming);
        cudaEventCreateWithFlags(&evJoin, cudaEventDisableTiming);
    }

    // Fork: edge_cat + packed mask on side stream, overlapping main-stream prologue
    cudaEventRecord(evFork, 0);
    cudaStreamWaitEvent(s2str, evFork, 0);
    edge2_kernel<<<ROWS, 256, 0, s2str>>>(A, out + ROWS*FF, ppm);
    cudaEventRecord(evJoin, s2str);

    // Main stream prologue: zero stats + s1 + s2, fp16 conversions, relayout
    zero3_kernel<<<(512 + 2*24576 + 255)/256, 256>>>(
        (float4*)pSt, 512, (float4*)ps1, 24576, (float4*)ps2, 24576);
    cvt_kernel<<<(CVT_TOT4+255)/256, 256>>>(X, W1, e_l0, e_l1, e_l2);
    wt_kernel<<<384, 256>>>(Ws);

    // Wh projection (batched over be) + fused s1/s2 dots (log2e-scaled)
    gemm4_kernel<1><<<dim3(SLOTS/64, NN/64, BE), 256>>>(
        pXH, pWtH, pWh, NN, SLOTS, FF,
        (long)NN*FF, (long)FF*SLOTS, (long)NN*SLOTS, EE, EE,
        1.f, nullptr, 0.f, nullptr, a1, a2, ps1, ps2);

    // Join: att5 needs pm from edge2
    cudaStreamWaitEvent(0, evJoin, 0);

    // fused masked softmax + P@Wh + ELU -> H
    att5_kernel<<<dim3(NN/32, BE), 256>>>(ppm, pWh, ps1, ps2, pH);

    // H @ W1 * 0.5 + 0.5*X -> bufA, stats0; bn1 -> HnH + HnF
    gemm4_kernel<0><<<dim3(FF/64, ROWS/64, 1), 256>>>(
        pH, pW1H, pA, ROWS, FF, HC, 0,0,0, 1,1,
        0.5f, X, 0.5f, pSt + 0, nullptr, nullptr, nullptr, nullptr);
    norm2_kernel<<<(ROWS*FF/4+255)/256, 256>>>(pA, pHnH, pHnF, pSt + 0, bn1_g, bn1_b, FF, 0);

    // Hn @ e_l0 -> bufA, stats1; elu(bn) -> Z0
    gemm4_kernel<0><<<dim3(L0C/64, ROWS/64, 1), 256>>>(
        pHnH, pL0H, pA, ROWS, L0C, FF, 0,0,0, 1,1,
        1.f, nullptr, 0.f, pSt + 512, nullptr, nullptr, nullptr, nullptr);
    norm2_kernel<<<(ROWS*L0C/4+255)/256, 256>>>(pA, pZ0, nullptr, pSt + 512, e_bn0g, e_bn0b, L0C, 1);

    // Z0 @ e_l1 -> bufA, stats2; elu(bn) -> Z1
    gemm4_kernel<0><<<dim3(L1C/64, ROWS/64, 1), 256>>>(
        pZ0, pL1H, pA, ROWS, L1C, L0C, 0,0,0, 1,1,
        1.f, nullptr, 0.f, pSt + 1024, nullptr, nullptr, nullptr, nullptr);
    norm2_kernel<<<(ROWS*L1C/4+255)/256, 256>>>(pA, pZ1, nullptr, pSt + 1024, e_bn1g, e_bn1b, L1C, 1);

    // Z1 @ e_l2 + HnF -> bufA, stats3; bn2 -> out
    gemm4_kernel<0><<<dim3(FF/64, ROWS/64, 1), 256>>>(
        pZ1, pL2H, pA, ROWS, FF, L1C, 0,0,0, 1,1,
        1.f, pHnF, 1.f, pSt + 1536, nullptr, nullptr, nullptr, nullptr);
    norm2_kernel<<<(ROWS*FF/4+255)/256, 256>>>(pA, nullptr, out, pSt + 1536, bn2_g, bn2_b, FF, 0);
}